// round 7
// baseline (speedup 1.0000x reference)
#include <cuda_runtime.h>
#include <cuda_bf16.h>
#include <math.h>
#include <stdint.h>

#define C_DIM 256
#define H_DIM 16
#define HS_DIM 16
#define B_DIM 64
#define T_DIM 256
#define M_DIM 16384
#define FF_DIM 1024
#define QKV_N 768
#define LN_EPS 1e-5f

// ---------------- scratch ----------------------------------------------------
__device__ float g_h1[M_DIM * C_DIM];
__device__ float g_qkv[M_DIM * QKV_N];
__device__ float g_attn[M_DIM * C_DIM];
__device__ float g_x1[M_DIM * C_DIM];
__device__ float g_h2[M_DIM * C_DIM];
__device__ float g_ffn1[M_DIM * FF_DIM];
__device__ float g_Wqkv[QKV_N * C_DIM];   // [N,K] K-major
__device__ float g_WpT[C_DIM * C_DIM];
__device__ float g_W1T[FF_DIM * C_DIM];
__device__ float g_W2T[C_DIM * FF_DIM];

// ---------------- helpers ----------------------------------------------------
__device__ __forceinline__ uint32_t smem_u32(const void* p) {
    uint32_t a;
    asm("{ .reg .u64 t; cvta.to.shared.u64 t, %1; cvt.u32.u64 %0, t; }" : "=r"(a) : "l"(p));
    return a;
}
__device__ __forceinline__ float to_tf32(float x) {
    uint32_t u;
    asm("cvt.rna.tf32.f32 %0, %1;" : "=r"(u) : "f"(x));
    return __uint_as_float(u);
}
static __device__ __forceinline__ void cp_async16(uint32_t dst, const void* src) {
    asm volatile("cp.async.cg.shared.global [%0], [%1], 16;" :: "r"(dst), "l"(src) : "memory");
}
#define CP_COMMIT() asm volatile("cp.async.commit_group;" ::: "memory")
template <int N> __device__ __forceinline__ void cp_wait() {
    asm volatile("cp.async.wait_group %0;" :: "n"(N) : "memory");
}

__device__ __forceinline__ void mma_tf32(float* c, uint32_t a0, uint32_t a1,
                                         uint32_t a2, uint32_t a3,
                                         uint32_t b0, uint32_t b1) {
    asm volatile(
        "mma.sync.aligned.m16n8k8.row.col.f32.tf32.tf32.f32 "
        "{%0,%1,%2,%3}, {%4,%5,%6,%7}, {%8,%9}, {%0,%1,%2,%3};"
        : "+f"(c[0]), "+f"(c[1]), "+f"(c[2]), "+f"(c[3])
        : "r"(a0), "r"(a1), "r"(a2), "r"(a3), "r"(b0), "r"(b1));
}

// ---------------- LayerNorm (output pre-rounded to tf32) ---------------------
__global__ void ln_kernel(const float* __restrict__ x, const float* __restrict__ g,
                          const float* __restrict__ b, float* __restrict__ out) {
    int row = blockIdx.x, tid = threadIdx.x;
    float v = x[(size_t)row * C_DIM + tid];
    float s = v, s2 = v * v;
    #pragma unroll
    for (int o = 16; o; o >>= 1) {
        s += __shfl_xor_sync(0xFFFFFFFFu, s, o);
        s2 += __shfl_xor_sync(0xFFFFFFFFu, s2, o);
    }
    __shared__ float ws[8], ws2[8];
    int w = tid >> 5, l = tid & 31;
    if (l == 0) { ws[w] = s; ws2[w] = s2; }
    __syncthreads();
    if (tid < 32) {
        float t1 = (tid < 8) ? ws[tid] : 0.f;
        float t2 = (tid < 8) ? ws2[tid] : 0.f;
        #pragma unroll
        for (int o = 4; o; o >>= 1) {
            t1 += __shfl_xor_sync(0xFFFFFFFFu, t1, o);
            t2 += __shfl_xor_sync(0xFFFFFFFFu, t2, o);
        }
        if (tid == 0) { ws[0] = t1; ws2[0] = t2; }
    }
    __syncthreads();
    float mean = ws[0] * (1.f / C_DIM);
    float var = ws2[0] * (1.f / C_DIM) - mean * mean;
    out[(size_t)row * C_DIM + tid] =
        to_tf32((v - mean) * rsqrtf(var + LN_EPS) * g[tid] + b[tid]);
}

// ---------------- weight repack to [N,K] K-major (pre-rounded) ---------------
__global__ void repack_qkv(const float* __restrict__ Wq, const float* __restrict__ Wk,
                           const float* __restrict__ Wv) {
    int i = blockIdx.x * blockDim.x + threadIdx.x;
    if (i >= QKV_N * C_DIM) return;
    int n = i >> 8, k = i & 255;
    int sel = n >> 8, nn = n & 255;
    int h = nn >> 4, d = nn & 15;
    int src = h * (C_DIM * HS_DIM) + k * HS_DIM + d;
    const float* W = (sel == 0) ? Wq : (sel == 1) ? Wk : Wv;
    g_Wqkv[i] = to_tf32(W[src]);
}
__global__ void repack_rest(const float* __restrict__ Wp, const float* __restrict__ W1,
                            const float* __restrict__ W2) {
    int i = blockIdx.x * blockDim.x + threadIdx.x;
    if (i < C_DIM * C_DIM) g_WpT[i] = to_tf32(Wp[(i & 255) * C_DIM + (i >> 8)]);
    if (i < FF_DIM * C_DIM) g_W1T[i] = to_tf32(W1[(i & 255) * FF_DIM + (i >> 8)]);
    if (i < C_DIM * FF_DIM) g_W2T[i] = to_tf32(W2[(i & 1023) * C_DIM + (i >> 10)]);
}

// ---------------- tf32 mma.sync GEMM, register-pipelined frags ---------------
#define TILE_F  (128 * 36)
#define TILE_B  (TILE_F * 4)
#define STAGE_B (2 * TILE_B)
#define GEMM_SMEM (3 * STAGE_B)

__device__ __forceinline__ void load_tile(uint32_t sdst, const float* __restrict__ gp,
                                          int ld, int row0, int kc, int tid) {
    #pragma unroll
    for (int i = 0; i < 4; i++) {
        int f = i * 256 + tid;
        int row = f >> 3;
        int c4 = (f & 7) * 4;
        cp_async16(sdst + (uint32_t)(row * 144 + c4 * 4),
                   gp + (size_t)(row0 + row) * ld + kc + c4);
    }
}

__device__ __forceinline__ void load_frags(const float* __restrict__ sA,
                                           const float* __restrict__ sB,
                                           int kk, int mbase, int nbase, int g, int t,
                                           uint32_t af[4][4], uint32_t bf[4][2]) {
    int k0 = kk * 8 + t;
    #pragma unroll
    for (int nt = 0; nt < 4; nt++) {
        int rn = nbase + nt * 8 + g;
        bf[nt][0] = __float_as_uint(sB[rn * 36 + k0]);
        bf[nt][1] = __float_as_uint(sB[rn * 36 + k0 + 4]);
    }
    #pragma unroll
    for (int mt = 0; mt < 4; mt++) {
        int r0 = mbase + mt * 16 + g;
        af[mt][0] = __float_as_uint(sA[r0 * 36 + k0]);
        af[mt][1] = __float_as_uint(sA[(r0 + 8) * 36 + k0]);
        af[mt][2] = __float_as_uint(sA[r0 * 36 + k0 + 4]);
        af[mt][3] = __float_as_uint(sA[(r0 + 8) * 36 + k0 + 4]);
    }
}

template <int EPI>
__global__ __launch_bounds__(256, 2) void mma_gemm(
    const float* __restrict__ A, const float* __restrict__ Bw,
    const float* __restrict__ bias, const float* __restrict__ resid,
    float* __restrict__ out, int M, int N, int K) {
    extern __shared__ float smem[];
    uint32_t sb = smem_u32(smem);
    int tid = threadIdx.x, wid = tid >> 5, lane = tid & 31;
    int g = lane >> 2, t = lane & 3;
    int warpM = wid & 1, warpN = wid >> 1;
    int mbase = warpM * 64, nbase = warpN * 32;
    int bm = blockIdx.y * 128, bn = blockIdx.x * 128;
    int nc = K >> 5;

    float acc[4][4][4];
    #pragma unroll
    for (int i = 0; i < 4; i++)
        #pragma unroll
        for (int j = 0; j < 4; j++)
            #pragma unroll
            for (int e = 0; e < 4; e++) acc[i][j][e] = 0.f;

    load_tile(sb, A, K, bm, 0, tid);
    load_tile(sb + TILE_B, Bw, K, bn, 0, tid);
    CP_COMMIT();
    load_tile(sb + STAGE_B, A, K, bm, 32, tid);
    load_tile(sb + STAGE_B + TILE_B, Bw, K, bn, 32, tid);
    CP_COMMIT();

    for (int c = 0; c < nc; c++) {
        if (c < nc - 1) cp_wait<1>(); else cp_wait<0>();
        __syncthreads();

        if (c + 2 < nc) {
            uint32_t st = sb + ((c + 2) % 3) * STAGE_B;
            load_tile(st, A, K, bm, (c + 2) << 5, tid);
            load_tile(st + TILE_B, Bw, K, bn, (c + 2) << 5, tid);
            CP_COMMIT();
        }

        const float* sA = smem + (c % 3) * (STAGE_B / 4);
        const float* sB = sA + TILE_F;

        // register-pipelined fragment loop: load kk+1 while issuing MMAs(kk)
        uint32_t af[2][4][4], bf[2][4][2];
        load_frags(sA, sB, 0, mbase, nbase, g, t, af[0], bf[0]);
        #pragma unroll
        for (int kk = 0; kk < 4; kk++) {
            int cur = kk & 1;
            if (kk < 3)
                load_frags(sA, sB, kk + 1, mbase, nbase, g, t, af[cur ^ 1], bf[cur ^ 1]);
            #pragma unroll
            for (int mt = 0; mt < 4; mt++)
                #pragma unroll
                for (int nt = 0; nt < 4; nt++)
                    mma_tf32(acc[mt][nt], af[cur][mt][0], af[cur][mt][1],
                             af[cur][mt][2], af[cur][mt][3],
                             bf[cur][nt][0], bf[cur][nt][1]);
        }
    }

    #pragma unroll
    for (int mt = 0; mt < 4; mt++) {
        int row = bm + mbase + mt * 16 + g;
        #pragma unroll
        for (int nt = 0; nt < 4; nt++) {
            int col = bn + nbase + nt * 8 + 2 * t;
            float2 v0 = make_float2(acc[mt][nt][0], acc[mt][nt][1]);
            float2 v1 = make_float2(acc[mt][nt][2], acc[mt][nt][3]);
            if (EPI >= 2) {
                float2 bv = *(const float2*)&bias[col];
                v0.x += bv.x; v0.y += bv.y; v1.x += bv.x; v1.y += bv.y;
            }
            if (EPI == 2) {
                v0.x = to_tf32(0.5f * v0.x * (1.f + erff(v0.x * 0.70710678118654752f)));
                v0.y = to_tf32(0.5f * v0.y * (1.f + erff(v0.y * 0.70710678118654752f)));
                v1.x = to_tf32(0.5f * v1.x * (1.f + erff(v1.x * 0.70710678118654752f)));
                v1.y = to_tf32(0.5f * v1.y * (1.f + erff(v1.y * 0.70710678118654752f)));
            }
            if (EPI == 3) {
                float2 r0 = *(const float2*)&resid[(size_t)row * N + col];
                float2 r1 = *(const float2*)&resid[(size_t)(row + 8) * N + col];
                v0.x += r0.x; v0.y += r0.y; v1.x += r1.x; v1.y += r1.y;
            }
            *(float2*)&out[(size_t)row * N + col] = v0;
            *(float2*)&out[(size_t)(row + 8) * N + col] = v1;
        }
    }
}

// ---------------- tensor-core flash attention (R6, unchanged) ----------------
#define QKV_PAD 18
#define P_PAD 66
#define SQ_OFF 0
#define SK_OFF (256 * QKV_PAD)
#define SV_OFF (512 * QKV_PAD)
#define SP_OFF (768 * QKV_PAD)
#define ATTN_SMEM ((768 * QKV_PAD + 8 * 16 * P_PAD) * 4)

__global__ __launch_bounds__(256) void attn_mma_kernel(const float* __restrict__ qkv,
                                                       float* __restrict__ out) {
    extern __shared__ float sm[];
    float* sQ = sm + SQ_OFF;
    float* sK = sm + SK_OFF;
    float* sV = sm + SV_OFF;
    int h = blockIdx.x, b = blockIdx.y;
    int tid = threadIdx.x, w = tid >> 5, lane = tid & 31;
    int g = lane >> 2, t = lane & 3;
    float* sP = sm + SP_OFF + w * (16 * P_PAD);

    {
        const float* rp = qkv + (size_t)(b * T_DIM + tid) * QKV_N + h * 16;
        #pragma unroll
        for (int d = 0; d < 16; d += 4) {
            float4 q4 = *(const float4*)&rp[d];
            sQ[tid * QKV_PAD + d]     = to_tf32(q4.x * 0.0625f);
            sQ[tid * QKV_PAD + d + 1] = to_tf32(q4.y * 0.0625f);
            sQ[tid * QKV_PAD + d + 2] = to_tf32(q4.z * 0.0625f);
            sQ[tid * QKV_PAD + d + 3] = to_tf32(q4.w * 0.0625f);
            float4 k4 = *(const float4*)&rp[256 + d];
            sK[tid * QKV_PAD + d]     = to_tf32(k4.x);
            sK[tid * QKV_PAD + d + 1] = to_tf32(k4.y);
            sK[tid * QKV_PAD + d + 2] = to_tf32(k4.z);
            sK[tid * QKV_PAD + d + 3] = to_tf32(k4.w);
            float4 v4 = *(const float4*)&rp[512 + d];
            sV[tid * QKV_PAD + d]     = to_tf32(v4.x);
            sV[tid * QKV_PAD + d + 1] = to_tf32(v4.y);
            sV[tid * QKV_PAD + d + 2] = to_tf32(v4.z);
            sV[tid * QKV_PAD + d + 3] = to_tf32(v4.w);
        }
    }
    __syncthreads();

    #pragma unroll
    for (int half = 0; half < 2; half++) {
        int rt = half ? (15 - w) : w;
        int r0 = rt * 16;
        int nkt = (rt >> 2) + 1;
        float m0 = -1e30f, m1 = -1e30f, l0 = 0.f, l1 = 0.f;
        float o[2][4] = {};

        for (int kt = 0; kt < nkt; kt++) {
            int kb = kt * 64;
            float s[8][4];
            #pragma unroll
            for (int nt = 0; nt < 8; nt++) {
                s[nt][0] = 0.f; s[nt][1] = 0.f; s[nt][2] = 0.f; s[nt][3] = 0.f;
            }
            #pragma unroll
            for (int ks = 0; ks < 2; ks++) {
                int k0 = ks * 8 + t;
                uint32_t a0 = __float_as_uint(sQ[(r0 + g) * QKV_PAD + k0]);
                uint32_t a1 = __float_as_uint(sQ[(r0 + g + 8) * QKV_PAD + k0]);
                uint32_t a2 = __float_as_uint(sQ[(r0 + g) * QKV_PAD + k0 + 4]);
                uint32_t a3 = __float_as_uint(sQ[(r0 + g + 8) * QKV_PAD + k0 + 4]);
                #pragma unroll
                for (int nt = 0; nt < 8; nt++) {
                    int rn = kb + nt * 8 + g;
                    uint32_t b0 = __float_as_uint(sK[rn * QKV_PAD + k0]);
                    uint32_t b1 = __float_as_uint(sK[rn * QKV_PAD + k0 + 4]);
                    mma_tf32(s[nt], a0, a1, a2, a3, b0, b1);
                }
            }
            if (kt == nkt - 1) {
                int rlo = r0 + g, rhi = r0 + g + 8;
                #pragma unroll
                for (int nt = 0; nt < 8; nt++) {
                    int c0 = kb + nt * 8 + 2 * t;
                    if (c0 > rlo) s[nt][0] = -1e30f;
                    if (c0 + 1 > rlo) s[nt][1] = -1e30f;
                    if (c0 > rhi) s[nt][2] = -1e30f;
                    if (c0 + 1 > rhi) s[nt][3] = -1e30f;
                }
            }
            float rm0 = -1e30f, rm1 = -1e30f;
            #pragma unroll
            for (int nt = 0; nt < 8; nt++) {
                rm0 = fmaxf(rm0, fmaxf(s[nt][0], s[nt][1]));
                rm1 = fmaxf(rm1, fmaxf(s[nt][2], s[nt][3]));
            }
            rm0 = fmaxf(rm0, __shfl_xor_sync(0xFFFFFFFFu, rm0, 1));
            rm0 = fmaxf(rm0, __shfl_xor_sync(0xFFFFFFFFu, rm0, 2));
            rm1 = fmaxf(rm1, __shfl_xor_sync(0xFFFFFFFFu, rm1, 1));
            rm1 = fmaxf(rm1, __shfl_xor_sync(0xFFFFFFFFu, rm1, 2));
            float mn0 = fmaxf(m0, rm0), mn1 = fmaxf(m1, rm1);
            float cf0 = __expf(m0 - mn0), cf1 = __expf(m1 - mn1);
            m0 = mn0; m1 = mn1;
            l0 *= cf0; l1 *= cf1;
            o[0][0] *= cf0; o[0][1] *= cf0; o[1][0] *= cf0; o[1][1] *= cf0;
            o[0][2] *= cf1; o[0][3] *= cf1; o[1][2] *= cf1; o[1][3] *= cf1;

            float ps0 = 0.f, ps1 = 0.f;
            #pragma unroll
            for (int nt = 0; nt < 8; nt++) {
                float p0 = __expf(s[nt][0] - m0);
                float p1 = __expf(s[nt][1] - m0);
                float p2 = __expf(s[nt][2] - m1);
                float p3 = __expf(s[nt][3] - m1);
                ps0 += p0 + p1; ps1 += p2 + p3;
                int cc = nt * 8 + 2 * t;
                sP[g * P_PAD + cc] = to_tf32(p0);
                sP[g * P_PAD + cc + 1] = to_tf32(p1);
                sP[(g + 8) * P_PAD + cc] = to_tf32(p2);
                sP[(g + 8) * P_PAD + cc + 1] = to_tf32(p3);
            }
            ps0 += __shfl_xor_sync(0xFFFFFFFFu, ps0, 1);
            ps0 += __shfl_xor_sync(0xFFFFFFFFu, ps0, 2);
            ps1 += __shfl_xor_sync(0xFFFFFFFFu, ps1, 1);
            ps1 += __shfl_xor_sync(0xFFFFFFFFu, ps1, 2);
            l0 += ps0; l1 += ps1;
            __syncwarp();

            #pragma unroll
            for (int ks = 0; ks < 8; ks++) {
                int k0 = ks * 8 + t;
                uint32_t a0 = __float_as_uint(sP[g * P_PAD + k0]);
                uint32_t a1 = __float_as_uint(sP[(g + 8) * P_PAD + k0]);
                uint32_t a2 = __float_as_uint(sP[g * P_PAD + k0 + 4]);
                uint32_t a3 = __float_as_uint(sP[(g + 8) * P_PAD + k0 + 4]);
                #pragma unroll
                for (int nt2 = 0; nt2 < 2; nt2++) {
                    uint32_t b0 = __float_as_uint(sV[(kb + k0) * QKV_PAD + nt2 * 8 + g]);
                    uint32_t b1 = __float_as_uint(sV[(kb + k0 + 4) * QKV_PAD + nt2 * 8 + g]);
                    mma_tf32(o[nt2], a0, a1, a2, a3, b0, b1);
                }
            }
            __syncwarp();
        }

        float i0 = 1.f / l0, i1 = 1.f / l1;
        #pragma unroll
        for (int nt2 = 0; nt2 < 2; nt2++) {
            int col = h * 16 + nt2 * 8 + 2 * t;
            float2 v0 = make_float2(to_tf32(o[nt2][0] * i0), to_tf32(o[nt2][1] * i0));
            float2 v1 = make_float2(to_tf32(o[nt2][2] * i1), to_tf32(o[nt2][3] * i1));
            *(float2*)&out[(size_t)(b * T_DIM + r0 + g) * C_DIM + col] = v0;
            *(float2*)&out[(size_t)(b * T_DIM + r0 + g + 8) * C_DIM + col] = v1;
        }
    }
}

// ---------------- launch -----------------------------------------------------
extern "C" void kernel_launch(void* const* d_in, const int* in_sizes, int n_in,
                              void* d_out, int out_size) {
    const float* x = (const float*)d_in[0];
    const float* Wq = (const float*)d_in[1];
    const float* Wk = (const float*)d_in[2];
    const float* Wv = (const float*)d_in[3];
    const float* Wp = (const float*)d_in[4];
    const float* bp = (const float*)d_in[5];
    const float* W1 = (const float*)d_in[6];
    const float* b1 = (const float*)d_in[7];
    const float* W2 = (const float*)d_in[8];
    const float* b2 = (const float*)d_in[9];
    const float* g1 = (const float*)d_in[10];
    const float* be1 = (const float*)d_in[11];
    const float* g2 = (const float*)d_in[12];
    const float* be2 = (const float*)d_in[13];
    float* out = (float*)d_out;

    float *h1, *qkv, *attn, *x1, *h2, *ffn1, *Wqkv, *WpT, *W1T, *W2T;
    cudaGetSymbolAddress((void**)&h1, g_h1);
    cudaGetSymbolAddress((void**)&qkv, g_qkv);
    cudaGetSymbolAddress((void**)&attn, g_attn);
    cudaGetSymbolAddress((void**)&x1, g_x1);
    cudaGetSymbolAddress((void**)&h2, g_h2);
    cudaGetSymbolAddress((void**)&ffn1, g_ffn1);
    cudaGetSymbolAddress((void**)&Wqkv, g_Wqkv);
    cudaGetSymbolAddress((void**)&WpT, g_WpT);
    cudaGetSymbolAddress((void**)&W1T, g_W1T);
    cudaGetSymbolAddress((void**)&W2T, g_W2T);

    cudaFuncSetAttribute(mma_gemm<0>, cudaFuncAttributeMaxDynamicSharedMemorySize, GEMM_SMEM);
    cudaFuncSetAttribute(mma_gemm<2>, cudaFuncAttributeMaxDynamicSharedMemorySize, GEMM_SMEM);
    cudaFuncSetAttribute(mma_gemm<3>, cudaFuncAttributeMaxDynamicSharedMemorySize, GEMM_SMEM);
    cudaFuncSetAttribute(attn_mma_kernel, cudaFuncAttributeMaxDynamicSharedMemorySize, ATTN_SMEM);

    ln_kernel<<<M_DIM, 256>>>(x, g1, be1, h1);
    repack_qkv<<<(QKV_N * C_DIM + 255) / 256, 256>>>(Wq, Wk, Wv);
    repack_rest<<<(FF_DIM * C_DIM + 255) / 256, 256>>>(Wp, W1, W2);

    // QKV: [M,256] @ [256,768]
    mma_gemm<0><<<dim3(QKV_N / 128, M_DIM / 128), 256, GEMM_SMEM>>>(
        h1, Wqkv, nullptr, nullptr, qkv, M_DIM, QKV_N, C_DIM);
    attn_mma_kernel<<<dim3(H_DIM, B_DIM), 256, ATTN_SMEM>>>(qkv, attn);
    // proj + bias + residual(x)
    mma_gemm<3><<<dim3(C_DIM / 128, M_DIM / 128), 256, GEMM_SMEM>>>(
        attn, WpT, bp, x, x1, M_DIM, C_DIM, C_DIM);
    ln_kernel<<<M_DIM, 256>>>(x1, g2, be2, h2);
    // FFN up + GELU
    mma_gemm<2><<<dim3(FF_DIM / 128, M_DIM / 128), 256, GEMM_SMEM>>>(
        h2, W1T, b1, nullptr, ffn1, M_DIM, FF_DIM, C_DIM);
    // FFN down + bias + residual(x1)
    mma_gemm<3><<<dim3(C_DIM / 128, M_DIM / 128), 256, GEMM_SMEM>>>(
        ffn1, W2T, b2, x1, out, M_DIM, C_DIM, FF_DIM);
}

// round 10
// speedup vs baseline: 1.0105x; 1.0105x over previous
#include <cuda_runtime.h>
#include <cuda_bf16.h>
#include <math.h>
#include <stdint.h>

#define C_DIM 256
#define H_DIM 16
#define HS_DIM 16
#define B_DIM 64
#define T_DIM 256
#define M_DIM 16384
#define FF_DIM 1024
#define QKV_N 768
#define LN_EPS 1e-5f

// ---------------- scratch ----------------------------------------------------
__device__ float g_h1[M_DIM * C_DIM];
__device__ float g_qkv[M_DIM * QKV_N];
__device__ float g_attn[M_DIM * C_DIM];
__device__ float g_x1[M_DIM * C_DIM];
__device__ float g_h2[M_DIM * C_DIM];
__device__ float g_ffn1[M_DIM * FF_DIM];
__device__ float g_Wqkv[QKV_N * C_DIM];   // [N,K] K-major
__device__ float g_WpT[C_DIM * C_DIM];
__device__ float g_W1T[FF_DIM * C_DIM];
__device__ float g_W2T[C_DIM * FF_DIM];

// ---------------- helpers ----------------------------------------------------
__device__ __forceinline__ uint32_t smem_u32(const void* p) {
    uint32_t a;
    asm("{ .reg .u64 t; cvta.to.shared.u64 t, %1; cvt.u32.u64 %0, t; }" : "=r"(a) : "l"(p));
    return a;
}
__device__ __forceinline__ float to_tf32(float x) {
    uint32_t u;
    asm("cvt.rna.tf32.f32 %0, %1;" : "=r"(u) : "f"(x));
    return __uint_as_float(u);
}
static __device__ __forceinline__ void cp_async16(uint32_t dst, const void* src) {
    asm volatile("cp.async.cg.shared.global [%0], [%1], 16;" :: "r"(dst), "l"(src) : "memory");
}
#define CP_COMMIT() asm volatile("cp.async.commit_group;" ::: "memory")
template <int N> __device__ __forceinline__ void cp_wait() {
    asm volatile("cp.async.wait_group %0;" :: "n"(N) : "memory");
}

__device__ __forceinline__ void mma_tf32(float* c, uint32_t a0, uint32_t a1,
                                         uint32_t a2, uint32_t a3,
                                         uint32_t b0, uint32_t b1) {
    asm volatile(
        "mma.sync.aligned.m16n8k8.row.col.f32.tf32.tf32.f32 "
        "{%0,%1,%2,%3}, {%4,%5,%6,%7}, {%8,%9}, {%0,%1,%2,%3};"
        : "+f"(c[0]), "+f"(c[1]), "+f"(c[2]), "+f"(c[3])
        : "r"(a0), "r"(a1), "r"(a2), "r"(a3), "r"(b0), "r"(b1));
}

// ---------------- LayerNorm (output pre-rounded to tf32) ---------------------
__global__ void ln_kernel(const float* __restrict__ x, const float* __restrict__ g,
                          const float* __restrict__ b, float* __restrict__ out) {
    int row = blockIdx.x, tid = threadIdx.x;
    float v = x[(size_t)row * C_DIM + tid];
    float s = v, s2 = v * v;
    #pragma unroll
    for (int o = 16; o; o >>= 1) {
        s += __shfl_xor_sync(0xFFFFFFFFu, s, o);
        s2 += __shfl_xor_sync(0xFFFFFFFFu, s2, o);
    }
    __shared__ float ws[8], ws2[8];
    int w = tid >> 5, l = tid & 31;
    if (l == 0) { ws[w] = s; ws2[w] = s2; }
    __syncthreads();
    if (tid < 32) {
        float t1 = (tid < 8) ? ws[tid] : 0.f;
        float t2 = (tid < 8) ? ws2[tid] : 0.f;
        #pragma unroll
        for (int o = 4; o; o >>= 1) {
            t1 += __shfl_xor_sync(0xFFFFFFFFu, t1, o);
            t2 += __shfl_xor_sync(0xFFFFFFFFu, t2, o);
        }
        if (tid == 0) { ws[0] = t1; ws2[0] = t2; }
    }
    __syncthreads();
    float mean = ws[0] * (1.f / C_DIM);
    float var = ws2[0] * (1.f / C_DIM) - mean * mean;
    out[(size_t)row * C_DIM + tid] =
        to_tf32((v - mean) * rsqrtf(var + LN_EPS) * g[tid] + b[tid]);
}

// ---------------- weight repack to [N,K] K-major (pre-rounded) ---------------
__global__ void repack_qkv(const float* __restrict__ Wq, const float* __restrict__ Wk,
                           const float* __restrict__ Wv) {
    int i = blockIdx.x * blockDim.x + threadIdx.x;
    if (i >= QKV_N * C_DIM) return;
    int n = i >> 8, k = i & 255;
    int sel = n >> 8, nn = n & 255;
    int h = nn >> 4, d = nn & 15;
    int src = h * (C_DIM * HS_DIM) + k * HS_DIM + d;
    const float* W = (sel == 0) ? Wq : (sel == 1) ? Wk : Wv;
    g_Wqkv[i] = to_tf32(W[src]);
}
__global__ void repack_rest(const float* __restrict__ Wp, const float* __restrict__ W1,
                            const float* __restrict__ W2) {
    int i = blockIdx.x * blockDim.x + threadIdx.x;
    if (i < C_DIM * C_DIM) g_WpT[i] = to_tf32(Wp[(i & 255) * C_DIM + (i >> 8)]);
    if (i < FF_DIM * C_DIM) g_W1T[i] = to_tf32(W1[(i & 255) * FF_DIM + (i >> 8)]);
    if (i < C_DIM * FF_DIM) g_W2T[i] = to_tf32(W2[(i & 1023) * C_DIM + (i >> 10)]);
}

// ---------------- tf32 mma.sync GEMM: 512 threads, warp tile 32x32 -----------
// CTA tile 128x128, BK=32, 16 warps (4M x 4N). 3-stage ring, one sync/chunk.
// TLP experiment: 8 warps/SMSP (2x the 256-thread config) to hide LDS latency.
#define TILE_F  (128 * 36)
#define TILE_B  (TILE_F * 4)
#define STAGE_B (2 * TILE_B)
#define GEMM_SMEM (3 * STAGE_B)    // 110592 B; 2 CTA/SM = 221 KB <= 227 KB

__device__ __forceinline__ void load_tile512(uint32_t sdst, const float* __restrict__ gp,
                                             int ld, int row0, int kc, int tid) {
    #pragma unroll
    for (int i = 0; i < 2; i++) {
        int f = i * 512 + tid;       // float4 index over 128x32
        int row = f >> 3;
        int c4 = (f & 7) * 4;
        cp_async16(sdst + (uint32_t)(row * 144 + c4 * 4),
                   gp + (size_t)(row0 + row) * ld + kc + c4);
    }
}

template <int EPI>
__global__ __launch_bounds__(512, 2) void mma_gemm(
    const float* __restrict__ A, const float* __restrict__ Bw,
    const float* __restrict__ bias, const float* __restrict__ resid,
    float* __restrict__ out, int M, int N, int K) {
    extern __shared__ float smem[];
    uint32_t sb = smem_u32(smem);
    int tid = threadIdx.x, wid = tid >> 5, lane = tid & 31;
    int g = lane >> 2, t = lane & 3;
    int warpM = wid & 3, warpN = wid >> 2;          // 4 x 4 warp grid
    int mbase = warpM * 32, nbase = warpN * 32;
    int bm = blockIdx.y * 128, bn = blockIdx.x * 128;
    int nc = K >> 5;

    float acc[2][4][4];
    #pragma unroll
    for (int i = 0; i < 2; i++)
        #pragma unroll
        for (int j = 0; j < 4; j++)
            #pragma unroll
            for (int e = 0; e < 4; e++) acc[i][j][e] = 0.f;

    load_tile512(sb, A, K, bm, 0, tid);
    load_tile512(sb + TILE_B, Bw, K, bn, 0, tid);
    CP_COMMIT();
    load_tile512(sb + STAGE_B, A, K, bm, 32, tid);
    load_tile512(sb + STAGE_B + TILE_B, Bw, K, bn, 32, tid);
    CP_COMMIT();

    for (int c = 0; c < nc; c++) {
        if (c < nc - 1) cp_wait<1>(); else cp_wait<0>();
        __syncthreads();

        if (c + 2 < nc) {
            uint32_t st = sb + ((c + 2) % 3) * STAGE_B;
            load_tile512(st, A, K, bm, (c + 2) << 5, tid);
            load_tile512(st + TILE_B, Bw, K, bn, (c + 2) << 5, tid);
            CP_COMMIT();
        }

        const float* sA = smem + (c % 3) * (STAGE_B / 4);
        const float* sB = sA + TILE_F;
        #pragma unroll
        for (int kk = 0; kk < 4; kk++) {
            int k0 = kk * 8 + t;
            uint32_t bf[4][2];
            #pragma unroll
            for (int nt = 0; nt < 4; nt++) {
                int rn = nbase + nt * 8 + g;
                bf[nt][0] = __float_as_uint(sB[rn * 36 + k0]);
                bf[nt][1] = __float_as_uint(sB[rn * 36 + k0 + 4]);
            }
            #pragma unroll
            for (int mt = 0; mt < 2; mt++) {
                int r0 = mbase + mt * 16 + g;
                uint32_t a0 = __float_as_uint(sA[r0 * 36 + k0]);
                uint32_t a1 = __float_as_uint(sA[(r0 + 8) * 36 + k0]);
                uint32_t a2 = __float_as_uint(sA[r0 * 36 + k0 + 4]);
                uint32_t a3 = __float_as_uint(sA[(r0 + 8) * 36 + k0 + 4]);
                #pragma unroll
                for (int nt = 0; nt < 4; nt++)
                    mma_tf32(acc[mt][nt], a0, a1, a2, a3, bf[nt][0], bf[nt][1]);
            }
        }
    }

    #pragma unroll
    for (int mt = 0; mt < 2; mt++) {
        int row = bm + mbase + mt * 16 + g;
        #pragma unroll
        for (int nt = 0; nt < 4; nt++) {
            int col = bn + nbase + nt * 8 + 2 * t;
            float2 v0 = make_float2(acc[mt][nt][0], acc[mt][nt][1]);
            float2 v1 = make_float2(acc[mt][nt][2], acc[mt][nt][3]);
            if (EPI >= 2) {
                float2 bv = *(const float2*)&bias[col];
                v0.x += bv.x; v0.y += bv.y; v1.x += bv.x; v1.y += bv.y;
            }
            if (EPI == 2) {
                v0.x = to_tf32(0.5f * v0.x * (1.f + erff(v0.x * 0.70710678118654752f)));
                v0.y = to_tf32(0.5f * v0.y * (1.f + erff(v0.y * 0.70710678118654752f)));
                v1.x = to_tf32(0.5f * v1.x * (1.f + erff(v1.x * 0.70710678118654752f)));
                v1.y = to_tf32(0.5f * v1.y * (1.f + erff(v1.y * 0.70710678118654752f)));
            }
            if (EPI == 3) {
                float2 r0 = *(const float2*)&resid[(size_t)row * N + col];
                float2 r1 = *(const float2*)&resid[(size_t)(row + 8) * N + col];
                v0.x += r0.x; v0.y += r0.y; v1.x += r1.x; v1.y += r1.y;
            }
            *(float2*)&out[(size_t)row * N + col] = v0;
            *(float2*)&out[(size_t)(row + 8) * N + col] = v1;
        }
    }
}

// ---------------- tensor-core flash attention (R6, unchanged) ----------------
#define QKV_PAD 18
#define P_PAD 66
#define SQ_OFF 0
#define SK_OFF (256 * QKV_PAD)
#define SV_OFF (512 * QKV_PAD)
#define SP_OFF (768 * QKV_PAD)
#define ATTN_SMEM ((768 * QKV_PAD + 8 * 16 * P_PAD) * 4)

__global__ __launch_bounds__(256) void attn_mma_kernel(const float* __restrict__ qkv,
                                                       float* __restrict__ out) {
    extern __shared__ float sm[];
    float* sQ = sm + SQ_OFF;
    float* sK = sm + SK_OFF;
    float* sV = sm + SV_OFF;
    int h = blockIdx.x, b = blockIdx.y;
    int tid = threadIdx.x, w = tid >> 5, lane = tid & 31;
    int g = lane >> 2, t = lane & 3;
    float* sP = sm + SP_OFF + w * (16 * P_PAD);

    {
        const float* rp = qkv + (size_t)(b * T_DIM + tid) * QKV_N + h * 16;
        #pragma unroll
        for (int d = 0; d < 16; d += 4) {
            float4 q4 = *(const float4*)&rp[d];
            sQ[tid * QKV_PAD + d]     = to_tf32(q4.x * 0.0625f);
            sQ[tid * QKV_PAD + d + 1] = to_tf32(q4.y * 0.0625f);
            sQ[tid * QKV_PAD + d + 2] = to_tf32(q4.z * 0.0625f);
            sQ[tid * QKV_PAD + d + 3] = to_tf32(q4.w * 0.0625f);
            float4 k4 = *(const float4*)&rp[256 + d];
            sK[tid * QKV_PAD + d]     = to_tf32(k4.x);
            sK[tid * QKV_PAD + d + 1] = to_tf32(k4.y);
            sK[tid * QKV_PAD + d + 2] = to_tf32(k4.z);
            sK[tid * QKV_PAD + d + 3] = to_tf32(k4.w);
            float4 v4 = *(const float4*)&rp[512 + d];
            sV[tid * QKV_PAD + d]     = to_tf32(v4.x);
            sV[tid * QKV_PAD + d + 1] = to_tf32(v4.y);
            sV[tid * QKV_PAD + d + 2] = to_tf32(v4.z);
            sV[tid * QKV_PAD + d + 3] = to_tf32(v4.w);
        }
    }
    __syncthreads();

    #pragma unroll
    for (int half = 0; half < 2; half++) {
        int rt = half ? (15 - w) : w;
        int r0 = rt * 16;
        int nkt = (rt >> 2) + 1;
        float m0 = -1e30f, m1 = -1e30f, l0 = 0.f, l1 = 0.f;
        float o[2][4] = {};

        for (int kt = 0; kt < nkt; kt++) {
            int kb = kt * 64;
            float s[8][4];
            #pragma unroll
            for (int nt = 0; nt < 8; nt++) {
                s[nt][0] = 0.f; s[nt][1] = 0.f; s[nt][2] = 0.f; s[nt][3] = 0.f;
            }
            #pragma unroll
            for (int ks = 0; ks < 2; ks++) {
                int k0 = ks * 8 + t;
                uint32_t a0 = __float_as_uint(sQ[(r0 + g) * QKV_PAD + k0]);
                uint32_t a1 = __float_as_uint(sQ[(r0 + g + 8) * QKV_PAD + k0]);
                uint32_t a2 = __float_as_uint(sQ[(r0 + g) * QKV_PAD + k0 + 4]);
                uint32_t a3 = __float_as_uint(sQ[(r0 + g + 8) * QKV_PAD + k0 + 4]);
                #pragma unroll
                for (int nt = 0; nt < 8; nt++) {
                    int rn = kb + nt * 8 + g;
                    uint32_t b0 = __float_as_uint(sK[rn * QKV_PAD + k0]);
                    uint32_t b1 = __float_as_uint(sK[rn * QKV_PAD + k0 + 4]);
                    mma_tf32(s[nt], a0, a1, a2, a3, b0, b1);
                }
            }
            if (kt == nkt - 1) {
                int rlo = r0 + g, rhi = r0 + g + 8;
                #pragma unroll
                for (int nt = 0; nt < 8; nt++) {
                    int c0 = kb + nt * 8 + 2 * t;
                    if (c0 > rlo) s[nt][0] = -1e30f;
                    if (c0 + 1 > rlo) s[nt][1] = -1e30f;
                    if (c0 > rhi) s[nt][2] = -1e30f;
                    if (c0 + 1 > rhi) s[nt][3] = -1e30f;
                }
            }
            float rm0 = -1e30f, rm1 = -1e30f;
            #pragma unroll
            for (int nt = 0; nt < 8; nt++) {
                rm0 = fmaxf(rm0, fmaxf(s[nt][0], s[nt][1]));
                rm1 = fmaxf(rm1, fmaxf(s[nt][2], s[nt][3]));
            }
            rm0 = fmaxf(rm0, __shfl_xor_sync(0xFFFFFFFFu, rm0, 1));
            rm0 = fmaxf(rm0, __shfl_xor_sync(0xFFFFFFFFu, rm0, 2));
            rm1 = fmaxf(rm1, __shfl_xor_sync(0xFFFFFFFFu, rm1, 1));
            rm1 = fmaxf(rm1, __shfl_xor_sync(0xFFFFFFFFu, rm1, 2));
            float mn0 = fmaxf(m0, rm0), mn1 = fmaxf(m1, rm1);
            float cf0 = __expf(m0 - mn0), cf1 = __expf(m1 - mn1);
            m0 = mn0; m1 = mn1;
            l0 *= cf0; l1 *= cf1;
            o[0][0] *= cf0; o[0][1] *= cf0; o[1][0] *= cf0; o[1][1] *= cf0;
            o[0][2] *= cf1; o[0][3] *= cf1; o[1][2] *= cf1; o[1][3] *= cf1;

            float ps0 = 0.f, ps1 = 0.f;
            #pragma unroll
            for (int nt = 0; nt < 8; nt++) {
                float p0 = __expf(s[nt][0] - m0);
                float p1 = __expf(s[nt][1] - m0);
                float p2 = __expf(s[nt][2] - m1);
                float p3 = __expf(s[nt][3] - m1);
                ps0 += p0 + p1; ps1 += p2 + p3;
                int cc = nt * 8 + 2 * t;
                sP[g * P_PAD + cc] = to_tf32(p0);
                sP[g * P_PAD + cc + 1] = to_tf32(p1);
                sP[(g + 8) * P_PAD + cc] = to_tf32(p2);
                sP[(g + 8) * P_PAD + cc + 1] = to_tf32(p3);
            }
            ps0 += __shfl_xor_sync(0xFFFFFFFFu, ps0, 1);
            ps0 += __shfl_xor_sync(0xFFFFFFFFu, ps0, 2);
            ps1 += __shfl_xor_sync(0xFFFFFFFFu, ps1, 1);
            ps1 += __shfl_xor_sync(0xFFFFFFFFu, ps1, 2);
            l0 += ps0; l1 += ps1;
            __syncwarp();

            #pragma unroll
            for (int ks = 0; ks < 8; ks++) {
                int k0 = ks * 8 + t;
                uint32_t a0 = __float_as_uint(sP[g * P_PAD + k0]);
                uint32_t a1 = __float_as_uint(sP[(g + 8) * P_PAD + k0]);
                uint32_t a2 = __float_as_uint(sP[g * P_PAD + k0 + 4]);
                uint32_t a3 = __float_as_uint(sP[(g + 8) * P_PAD + k0 + 4]);
                #pragma unroll
                for (int nt2 = 0; nt2 < 2; nt2++) {
                    uint32_t b0 = __float_as_uint(sV[(kb + k0) * QKV_PAD + nt2 * 8 + g]);
                    uint32_t b1 = __float_as_uint(sV[(kb + k0 + 4) * QKV_PAD + nt2 * 8 + g]);
                    mma_tf32(o[nt2], a0, a1, a2, a3, b0, b1);
                }
            }
            __syncwarp();
        }

        float i0 = 1.f / l0, i1 = 1.f / l1;
        #pragma unroll
        for (int nt2 = 0; nt2 < 2; nt2++) {
            int col = h * 16 + nt2 * 8 + 2 * t;
            float2 v0 = make_float2(to_tf32(o[nt2][0] * i0), to_tf32(o[nt2][1] * i0));
            float2 v1 = make_float2(to_tf32(o[nt2][2] * i1), to_tf32(o[nt2][3] * i1));
            *(float2*)&out[(size_t)(b * T_DIM + r0 + g) * C_DIM + col] = v0;
            *(float2*)&out[(size_t)(b * T_DIM + r0 + g + 8) * C_DIM + col] = v1;
        }
    }
}

// ---------------- launch -----------------------------------------------------
extern "C" void kernel_launch(void* const* d_in, const int* in_sizes, int n_in,
                              void* d_out, int out_size) {
    const float* x = (const float*)d_in[0];
    const float* Wq = (const float*)d_in[1];
    const float* Wk = (const float*)d_in[2];
    const float* Wv = (const float*)d_in[3];
    const float* Wp = (const float*)d_in[4];
    const float* bp = (const float*)d_in[5];
    const float* W1 = (const float*)d_in[6];
    const float* b1 = (const float*)d_in[7];
    const float* W2 = (const float*)d_in[8];
    const float* b2 = (const float*)d_in[9];
    const float* g1 = (const float*)d_in[10];
    const float* be1 = (const float*)d_in[11];
    const float* g2 = (const float*)d_in[12];
    const float* be2 = (const float*)d_in[13];
    float* out = (float*)d_out;

    float *h1, *qkv, *attn, *x1, *h2, *ffn1, *Wqkv, *WpT, *W1T, *W2T;
    cudaGetSymbolAddress((void**)&h1, g_h1);
    cudaGetSymbolAddress((void**)&qkv, g_qkv);
    cudaGetSymbolAddress((void**)&attn, g_attn);
    cudaGetSymbolAddress((void**)&x1, g_x1);
    cudaGetSymbolAddress((void**)&h2, g_h2);
    cudaGetSymbolAddress((void**)&ffn1, g_ffn1);
    cudaGetSymbolAddress((void**)&Wqkv, g_Wqkv);
    cudaGetSymbolAddress((void**)&WpT, g_WpT);
    cudaGetSymbolAddress((void**)&W1T, g_W1T);
    cudaGetSymbolAddress((void**)&W2T, g_W2T);

    cudaFuncSetAttribute(mma_gemm<0>, cudaFuncAttributeMaxDynamicSharedMemorySize, GEMM_SMEM);
    cudaFuncSetAttribute(mma_gemm<2>, cudaFuncAttributeMaxDynamicSharedMemorySize, GEMM_SMEM);
    cudaFuncSetAttribute(mma_gemm<3>, cudaFuncAttributeMaxDynamicSharedMemorySize, GEMM_SMEM);
    cudaFuncSetAttribute(attn_mma_kernel, cudaFuncAttributeMaxDynamicSharedMemorySize, ATTN_SMEM);

    ln_kernel<<<M_DIM, 256>>>(x, g1, be1, h1);
    repack_qkv<<<(QKV_N * C_DIM + 255) / 256, 256>>>(Wq, Wk, Wv);
    repack_rest<<<(FF_DIM * C_DIM + 255) / 256, 256>>>(Wp, W1, W2);

    // QKV: [M,256] @ [256,768]
    mma_gemm<0><<<dim3(QKV_N / 128, M_DIM / 128), 512, GEMM_SMEM>>>(
        h1, Wqkv, nullptr, nullptr, qkv, M_DIM, QKV_N, C_DIM);
    attn_mma_kernel<<<dim3(H_DIM, B_DIM), 256, ATTN_SMEM>>>(qkv, attn);
    // proj + bias + residual(x)
    mma_gemm<3><<<dim3(C_DIM / 128, M_DIM / 128), 512, GEMM_SMEM>>>(
        attn, WpT, bp, x, x1, M_DIM, C_DIM, C_DIM);
    ln_kernel<<<M_DIM, 256>>>(x1, g2, be2, h2);
    // FFN up + GELU
    mma_gemm<2><<<dim3(FF_DIM / 128, M_DIM / 128), 512, GEMM_SMEM>>>(
        h2, W1T, b1, nullptr, ffn1, M_DIM, FF_DIM, C_DIM);
    // FFN down + bias + residual(x1)
    mma_gemm<3><<<dim3(C_DIM / 128, M_DIM / 128), 512, GEMM_SMEM>>>(
        ffn1, W2T, b2, x1, out, M_DIM, C_DIM, FF_DIM);
}

// round 11
// speedup vs baseline: 1.0412x; 1.0304x over previous
#include <cuda_runtime.h>
#include <cuda_bf16.h>
#include <math.h>
#include <stdint.h>

#define C_DIM 256
#define H_DIM 16
#define HS_DIM 16
#define B_DIM 64
#define T_DIM 256
#define M_DIM 16384
#define FF_DIM 1024
#define QKV_N 768
#define LN_EPS 1e-5f

// ---------------- scratch ----------------------------------------------------
__device__ float g_h1[M_DIM * C_DIM];
__device__ float g_qkv[M_DIM * QKV_N];
__device__ float g_attn[M_DIM * C_DIM];
__device__ float g_x1[M_DIM * C_DIM];
__device__ float g_h2[M_DIM * C_DIM];
__device__ float g_ffn1[M_DIM * FF_DIM];
__device__ float g_Wqkv[QKV_N * C_DIM];   // [N,K] K-major
__device__ float g_WpT[C_DIM * C_DIM];
__device__ float g_W1T[FF_DIM * C_DIM];
__device__ float g_W2T[C_DIM * FF_DIM];

// ---------------- helpers ----------------------------------------------------
__device__ __forceinline__ uint32_t smem_u32(const void* p) {
    uint32_t a;
    asm("{ .reg .u64 t; cvta.to.shared.u64 t, %1; cvt.u32.u64 %0, t; }" : "=r"(a) : "l"(p));
    return a;
}
__device__ __forceinline__ float to_tf32(float x) {
    uint32_t u;
    asm("cvt.rna.tf32.f32 %0, %1;" : "=r"(u) : "f"(x));
    return __uint_as_float(u);
}
static __device__ __forceinline__ void cp_async16(uint32_t dst, const void* src) {
    asm volatile("cp.async.cg.shared.global [%0], [%1], 16;" :: "r"(dst), "l"(src) : "memory");
}
#define CP_COMMIT() asm volatile("cp.async.commit_group;" ::: "memory")
template <int N> __device__ __forceinline__ void cp_wait() {
    asm volatile("cp.async.wait_group %0;" :: "n"(N) : "memory");
}

__device__ __forceinline__ void mma_tf32(float* c, uint32_t a0, uint32_t a1,
                                         uint32_t a2, uint32_t a3,
                                         uint32_t b0, uint32_t b1) {
    asm volatile(
        "mma.sync.aligned.m16n8k8.row.col.f32.tf32.tf32.f32 "
        "{%0,%1,%2,%3}, {%4,%5,%6,%7}, {%8,%9}, {%0,%1,%2,%3};"
        : "+f"(c[0]), "+f"(c[1]), "+f"(c[2]), "+f"(c[3])
        : "r"(a0), "r"(a1), "r"(a2), "r"(a3), "r"(b0), "r"(b1));
}

// ---------------- LayerNorm (output pre-rounded to tf32) ---------------------
__global__ void ln_kernel(const float* __restrict__ x, const float* __restrict__ g,
                          const float* __restrict__ b, float* __restrict__ out) {
    int row = blockIdx.x, tid = threadIdx.x;
    float v = x[(size_t)row * C_DIM + tid];
    float s = v, s2 = v * v;
    #pragma unroll
    for (int o = 16; o; o >>= 1) {
        s += __shfl_xor_sync(0xFFFFFFFFu, s, o);
        s2 += __shfl_xor_sync(0xFFFFFFFFu, s2, o);
    }
    __shared__ float ws[8], ws2[8];
    int w = tid >> 5, l = tid & 31;
    if (l == 0) { ws[w] = s; ws2[w] = s2; }
    __syncthreads();
    if (tid < 32) {
        float t1 = (tid < 8) ? ws[tid] : 0.f;
        float t2 = (tid < 8) ? ws2[tid] : 0.f;
        #pragma unroll
        for (int o = 4; o; o >>= 1) {
            t1 += __shfl_xor_sync(0xFFFFFFFFu, t1, o);
            t2 += __shfl_xor_sync(0xFFFFFFFFu, t2, o);
        }
        if (tid == 0) { ws[0] = t1; ws2[0] = t2; }
    }
    __syncthreads();
    float mean = ws[0] * (1.f / C_DIM);
    float var = ws2[0] * (1.f / C_DIM) - mean * mean;
    out[(size_t)row * C_DIM + tid] =
        to_tf32((v - mean) * rsqrtf(var + LN_EPS) * g[tid] + b[tid]);
}

// ---------------- weight repacks ----------------------------------------------
// QKV: [H,C,HS] -> [N,K] K-major; reads are coalesced (d,k fastest = contiguous)
__global__ void repack_qkv(const float* __restrict__ Wq, const float* __restrict__ Wk,
                           const float* __restrict__ Wv) {
    int i = blockIdx.x * blockDim.x + threadIdx.x;
    if (i >= QKV_N * C_DIM) return;
    int n = i >> 8, k = i & 255;
    int sel = n >> 8, nn = n & 255;
    int h = nn >> 4, d = nn & 15;
    int src = h * (C_DIM * HS_DIM) + k * HS_DIM + d;
    const float* W = (sel == 0) ? Wq : (sel == 1) ? Wk : Wv;
    g_Wqkv[i] = to_tf32(W[src]);
}

// coalesced 32x32 smem-tiled transpose: src [rows, cols] -> dst [cols, rows],
// output pre-rounded to tf32. Block 32x8, 4 rows per thread. Replaces the
// fully-uncoalesced repack_rest (strided 4B reads, ~16-32x traffic blowup).
__global__ void transpose_tf32(const float* __restrict__ src, float* __restrict__ dst,
                               int rows, int cols) {
    __shared__ float tile[32][33];
    int bx = blockIdx.x * 32, by = blockIdx.y * 32;
    int tx = threadIdx.x, ty = threadIdx.y;
    #pragma unroll
    for (int j = 0; j < 32; j += 8)
        tile[ty + j][tx] = src[(size_t)(by + ty + j) * cols + bx + tx];
    __syncthreads();
    #pragma unroll
    for (int j = 0; j < 32; j += 8)
        dst[(size_t)(bx + ty + j) * rows + by + tx] = to_tf32(tile[tx][ty + j]);
}

// ---------------- tf32 mma.sync GEMM (R6 config: best measured) --------------
#define TILE_F  (128 * 36)
#define TILE_B  (TILE_F * 4)
#define STAGE_B (2 * TILE_B)
#define GEMM_SMEM (3 * STAGE_B)

__device__ __forceinline__ void load_tile(uint32_t sdst, const float* __restrict__ gp,
                                          int ld, int row0, int kc, int tid) {
    #pragma unroll
    for (int i = 0; i < 4; i++) {
        int f = i * 256 + tid;
        int row = f >> 3;
        int c4 = (f & 7) * 4;
        cp_async16(sdst + (uint32_t)(row * 144 + c4 * 4),
                   gp + (size_t)(row0 + row) * ld + kc + c4);
    }
}

template <int EPI>
__global__ __launch_bounds__(256, 2) void mma_gemm(
    const float* __restrict__ A, const float* __restrict__ Bw,
    const float* __restrict__ bias, const float* __restrict__ resid,
    float* __restrict__ out, int M, int N, int K) {
    extern __shared__ float smem[];
    uint32_t sb = smem_u32(smem);
    int tid = threadIdx.x, wid = tid >> 5, lane = tid & 31;
    int g = lane >> 2, t = lane & 3;
    int warpM = wid & 1, warpN = wid >> 1;
    int mbase = warpM * 64, nbase = warpN * 32;
    int bm = blockIdx.y * 128, bn = blockIdx.x * 128;
    int nc = K >> 5;

    float acc[4][4][4];
    #pragma unroll
    for (int i = 0; i < 4; i++)
        #pragma unroll
        for (int j = 0; j < 4; j++)
            #pragma unroll
            for (int e = 0; e < 4; e++) acc[i][j][e] = 0.f;

    load_tile(sb, A, K, bm, 0, tid);
    load_tile(sb + TILE_B, Bw, K, bn, 0, tid);
    CP_COMMIT();
    load_tile(sb + STAGE_B, A, K, bm, 32, tid);
    load_tile(sb + STAGE_B + TILE_B, Bw, K, bn, 32, tid);
    CP_COMMIT();

    for (int c = 0; c < nc; c++) {
        if (c < nc - 1) cp_wait<1>(); else cp_wait<0>();
        __syncthreads();

        if (c + 2 < nc) {
            uint32_t st = sb + ((c + 2) % 3) * STAGE_B;
            load_tile(st, A, K, bm, (c + 2) << 5, tid);
            load_tile(st + TILE_B, Bw, K, bn, (c + 2) << 5, tid);
            CP_COMMIT();
        }

        const float* sA = smem + (c % 3) * (STAGE_B / 4);
        const float* sB = sA + TILE_F;
        #pragma unroll
        for (int kk = 0; kk < 4; kk++) {
            int k0 = kk * 8 + t;
            uint32_t bf[4][2];
            #pragma unroll
            for (int nt = 0; nt < 4; nt++) {
                int rn = nbase + nt * 8 + g;
                bf[nt][0] = __float_as_uint(sB[rn * 36 + k0]);
                bf[nt][1] = __float_as_uint(sB[rn * 36 + k0 + 4]);
            }
            #pragma unroll
            for (int mt = 0; mt < 4; mt++) {
                int r0 = mbase + mt * 16 + g;
                uint32_t a0 = __float_as_uint(sA[r0 * 36 + k0]);
                uint32_t a1 = __float_as_uint(sA[(r0 + 8) * 36 + k0]);
                uint32_t a2 = __float_as_uint(sA[r0 * 36 + k0 + 4]);
                uint32_t a3 = __float_as_uint(sA[(r0 + 8) * 36 + k0 + 4]);
                #pragma unroll
                for (int nt = 0; nt < 4; nt++)
                    mma_tf32(acc[mt][nt], a0, a1, a2, a3, bf[nt][0], bf[nt][1]);
            }
        }
    }

    #pragma unroll
    for (int mt = 0; mt < 4; mt++) {
        int row = bm + mbase + mt * 16 + g;
        #pragma unroll
        for (int nt = 0; nt < 4; nt++) {
            int col = bn + nbase + nt * 8 + 2 * t;
            float2 v0 = make_float2(acc[mt][nt][0], acc[mt][nt][1]);
            float2 v1 = make_float2(acc[mt][nt][2], acc[mt][nt][3]);
            if (EPI >= 2) {
                float2 bv = *(const float2*)&bias[col];
                v0.x += bv.x; v0.y += bv.y; v1.x += bv.x; v1.y += bv.y;
            }
            if (EPI == 2) {
                v0.x = to_tf32(0.5f * v0.x * (1.f + erff(v0.x * 0.70710678118654752f)));
                v0.y = to_tf32(0.5f * v0.y * (1.f + erff(v0.y * 0.70710678118654752f)));
                v1.x = to_tf32(0.5f * v1.x * (1.f + erff(v1.x * 0.70710678118654752f)));
                v1.y = to_tf32(0.5f * v1.y * (1.f + erff(v1.y * 0.70710678118654752f)));
            }
            if (EPI == 3) {
                float2 r0 = *(const float2*)&resid[(size_t)row * N + col];
                float2 r1 = *(const float2*)&resid[(size_t)(row + 8) * N + col];
                v0.x += r0.x; v0.y += r0.y; v1.x += r1.x; v1.y += r1.y;
            }
            *(float2*)&out[(size_t)row * N + col] = v0;
            *(float2*)&out[(size_t)(row + 8) * N + col] = v1;
        }
    }
}

// ---------------- tensor-core flash attention (R6, unchanged) ----------------
#define QKV_PAD 18
#define P_PAD 66
#define SQ_OFF 0
#define SK_OFF (256 * QKV_PAD)
#define SV_OFF (512 * QKV_PAD)
#define SP_OFF (768 * QKV_PAD)
#define ATTN_SMEM ((768 * QKV_PAD + 8 * 16 * P_PAD) * 4)

__global__ __launch_bounds__(256) void attn_mma_kernel(const float* __restrict__ qkv,
                                                       float* __restrict__ out) {
    extern __shared__ float sm[];
    float* sQ = sm + SQ_OFF;
    float* sK = sm + SK_OFF;
    float* sV = sm + SV_OFF;
    int h = blockIdx.x, b = blockIdx.y;
    int tid = threadIdx.x, w = tid >> 5, lane = tid & 31;
    int g = lane >> 2, t = lane & 3;
    float* sP = sm + SP_OFF + w * (16 * P_PAD);

    {
        const float* rp = qkv + (size_t)(b * T_DIM + tid) * QKV_N + h * 16;
        #pragma unroll
        for (int d = 0; d < 16; d += 4) {
            float4 q4 = *(const float4*)&rp[d];
            sQ[tid * QKV_PAD + d]     = to_tf32(q4.x * 0.0625f);
            sQ[tid * QKV_PAD + d + 1] = to_tf32(q4.y * 0.0625f);
            sQ[tid * QKV_PAD + d + 2] = to_tf32(q4.z * 0.0625f);
            sQ[tid * QKV_PAD + d + 3] = to_tf32(q4.w * 0.0625f);
            float4 k4 = *(const float4*)&rp[256 + d];
            sK[tid * QKV_PAD + d]     = to_tf32(k4.x);
            sK[tid * QKV_PAD + d + 1] = to_tf32(k4.y);
            sK[tid * QKV_PAD + d + 2] = to_tf32(k4.z);
            sK[tid * QKV_PAD + d + 3] = to_tf32(k4.w);
            float4 v4 = *(const float4*)&rp[512 + d];
            sV[tid * QKV_PAD + d]     = to_tf32(v4.x);
            sV[tid * QKV_PAD + d + 1] = to_tf32(v4.y);
            sV[tid * QKV_PAD + d + 2] = to_tf32(v4.z);
            sV[tid * QKV_PAD + d + 3] = to_tf32(v4.w);
        }
    }
    __syncthreads();

    #pragma unroll
    for (int half = 0; half < 2; half++) {
        int rt = half ? (15 - w) : w;
        int r0 = rt * 16;
        int nkt = (rt >> 2) + 1;
        float m0 = -1e30f, m1 = -1e30f, l0 = 0.f, l1 = 0.f;
        float o[2][4] = {};

        for (int kt = 0; kt < nkt; kt++) {
            int kb = kt * 64;
            float s[8][4];
            #pragma unroll
            for (int nt = 0; nt < 8; nt++) {
                s[nt][0] = 0.f; s[nt][1] = 0.f; s[nt][2] = 0.f; s[nt][3] = 0.f;
            }
            #pragma unroll
            for (int ks = 0; ks < 2; ks++) {
                int k0 = ks * 8 + t;
                uint32_t a0 = __float_as_uint(sQ[(r0 + g) * QKV_PAD + k0]);
                uint32_t a1 = __float_as_uint(sQ[(r0 + g + 8) * QKV_PAD + k0]);
                uint32_t a2 = __float_as_uint(sQ[(r0 + g) * QKV_PAD + k0 + 4]);
                uint32_t a3 = __float_as_uint(sQ[(r0 + g + 8) * QKV_PAD + k0 + 4]);
                #pragma unroll
                for (int nt = 0; nt < 8; nt++) {
                    int rn = kb + nt * 8 + g;
                    uint32_t b0 = __float_as_uint(sK[rn * QKV_PAD + k0]);
                    uint32_t b1 = __float_as_uint(sK[rn * QKV_PAD + k0 + 4]);
                    mma_tf32(s[nt], a0, a1, a2, a3, b0, b1);
                }
            }
            if (kt == nkt - 1) {
                int rlo = r0 + g, rhi = r0 + g + 8;
                #pragma unroll
                for (int nt = 0; nt < 8; nt++) {
                    int c0 = kb + nt * 8 + 2 * t;
                    if (c0 > rlo) s[nt][0] = -1e30f;
                    if (c0 + 1 > rlo) s[nt][1] = -1e30f;
                    if (c0 > rhi) s[nt][2] = -1e30f;
                    if (c0 + 1 > rhi) s[nt][3] = -1e30f;
                }
            }
            float rm0 = -1e30f, rm1 = -1e30f;
            #pragma unroll
            for (int nt = 0; nt < 8; nt++) {
                rm0 = fmaxf(rm0, fmaxf(s[nt][0], s[nt][1]));
                rm1 = fmaxf(rm1, fmaxf(s[nt][2], s[nt][3]));
            }
            rm0 = fmaxf(rm0, __shfl_xor_sync(0xFFFFFFFFu, rm0, 1));
            rm0 = fmaxf(rm0, __shfl_xor_sync(0xFFFFFFFFu, rm0, 2));
            rm1 = fmaxf(rm1, __shfl_xor_sync(0xFFFFFFFFu, rm1, 1));
            rm1 = fmaxf(rm1, __shfl_xor_sync(0xFFFFFFFFu, rm1, 2));
            float mn0 = fmaxf(m0, rm0), mn1 = fmaxf(m1, rm1);
            float cf0 = __expf(m0 - mn0), cf1 = __expf(m1 - mn1);
            m0 = mn0; m1 = mn1;
            l0 *= cf0; l1 *= cf1;
            o[0][0] *= cf0; o[0][1] *= cf0; o[1][0] *= cf0; o[1][1] *= cf0;
            o[0][2] *= cf1; o[0][3] *= cf1; o[1][2] *= cf1; o[1][3] *= cf1;

            float ps0 = 0.f, ps1 = 0.f;
            #pragma unroll
            for (int nt = 0; nt < 8; nt++) {
                float p0 = __expf(s[nt][0] - m0);
                float p1 = __expf(s[nt][1] - m0);
                float p2 = __expf(s[nt][2] - m1);
                float p3 = __expf(s[nt][3] - m1);
                ps0 += p0 + p1; ps1 += p2 + p3;
                int cc = nt * 8 + 2 * t;
                sP[g * P_PAD + cc] = to_tf32(p0);
                sP[g * P_PAD + cc + 1] = to_tf32(p1);
                sP[(g + 8) * P_PAD + cc] = to_tf32(p2);
                sP[(g + 8) * P_PAD + cc + 1] = to_tf32(p3);
            }
            ps0 += __shfl_xor_sync(0xFFFFFFFFu, ps0, 1);
            ps0 += __shfl_xor_sync(0xFFFFFFFFu, ps0, 2);
            ps1 += __shfl_xor_sync(0xFFFFFFFFu, ps1, 1);
            ps1 += __shfl_xor_sync(0xFFFFFFFFu, ps1, 2);
            l0 += ps0; l1 += ps1;
            __syncwarp();

            #pragma unroll
            for (int ks = 0; ks < 8; ks++) {
                int k0 = ks * 8 + t;
                uint32_t a0 = __float_as_uint(sP[g * P_PAD + k0]);
                uint32_t a1 = __float_as_uint(sP[(g + 8) * P_PAD + k0]);
                uint32_t a2 = __float_as_uint(sP[g * P_PAD + k0 + 4]);
                uint32_t a3 = __float_as_uint(sP[(g + 8) * P_PAD + k0 + 4]);
                #pragma unroll
                for (int nt2 = 0; nt2 < 2; nt2++) {
                    uint32_t b0 = __float_as_uint(sV[(kb + k0) * QKV_PAD + nt2 * 8 + g]);
                    uint32_t b1 = __float_as_uint(sV[(kb + k0 + 4) * QKV_PAD + nt2 * 8 + g]);
                    mma_tf32(o[nt2], a0, a1, a2, a3, b0, b1);
                }
            }
            __syncwarp();
        }

        float i0 = 1.f / l0, i1 = 1.f / l1;
        #pragma unroll
        for (int nt2 = 0; nt2 < 2; nt2++) {
            int col = h * 16 + nt2 * 8 + 2 * t;
            float2 v0 = make_float2(to_tf32(o[nt2][0] * i0), to_tf32(o[nt2][1] * i0));
            float2 v1 = make_float2(to_tf32(o[nt2][2] * i1), to_tf32(o[nt2][3] * i1));
            *(float2*)&out[(size_t)(b * T_DIM + r0 + g) * C_DIM + col] = v0;
            *(float2*)&out[(size_t)(b * T_DIM + r0 + g + 8) * C_DIM + col] = v1;
        }
    }
}

// ---------------- launch -----------------------------------------------------
extern "C" void kernel_launch(void* const* d_in, const int* in_sizes, int n_in,
                              void* d_out, int out_size) {
    const float* x = (const float*)d_in[0];
    const float* Wq = (const float*)d_in[1];
    const float* Wk = (const float*)d_in[2];
    const float* Wv = (const float*)d_in[3];
    const float* Wp = (const float*)d_in[4];
    const float* bp = (const float*)d_in[5];
    const float* W1 = (const float*)d_in[6];
    const float* b1 = (const float*)d_in[7];
    const float* W2 = (const float*)d_in[8];
    const float* b2 = (const float*)d_in[9];
    const float* g1 = (const float*)d_in[10];
    const float* be1 = (const float*)d_in[11];
    const float* g2 = (const float*)d_in[12];
    const float* be2 = (const float*)d_in[13];
    float* out = (float*)d_out;

    float *h1, *qkv, *attn, *x1, *h2, *ffn1, *Wqkv, *WpT, *W1T, *W2T;
    cudaGetSymbolAddress((void**)&h1, g_h1);
    cudaGetSymbolAddress((void**)&qkv, g_qkv);
    cudaGetSymbolAddress((void**)&attn, g_attn);
    cudaGetSymbolAddress((void**)&x1, g_x1);
    cudaGetSymbolAddress((void**)&h2, g_h2);
    cudaGetSymbolAddress((void**)&ffn1, g_ffn1);
    cudaGetSymbolAddress((void**)&Wqkv, g_Wqkv);
    cudaGetSymbolAddress((void**)&WpT, g_WpT);
    cudaGetSymbolAddress((void**)&W1T, g_W1T);
    cudaGetSymbolAddress((void**)&W2T, g_W2T);

    cudaFuncSetAttribute(mma_gemm<0>, cudaFuncAttributeMaxDynamicSharedMemorySize, GEMM_SMEM);
    cudaFuncSetAttribute(mma_gemm<2>, cudaFuncAttributeMaxDynamicSharedMemorySize, GEMM_SMEM);
    cudaFuncSetAttribute(mma_gemm<3>, cudaFuncAttributeMaxDynamicSharedMemorySize, GEMM_SMEM);
    cudaFuncSetAttribute(attn_mma_kernel, cudaFuncAttributeMaxDynamicSharedMemorySize, ATTN_SMEM);

    ln_kernel<<<M_DIM, 256>>>(x, g1, be1, h1);
    repack_qkv<<<(QKV_N * C_DIM + 255) / 256, 256>>>(Wq, Wk, Wv);
    // coalesced tiled transposes (replaces uncoalesced repack_rest):
    dim3 tb(32, 8);
    transpose_tf32<<<dim3(C_DIM / 32, C_DIM / 32), tb>>>(Wp, WpT, C_DIM, C_DIM);
    transpose_tf32<<<dim3(FF_DIM / 32, C_DIM / 32), tb>>>(W1, W1T, C_DIM, FF_DIM);
    transpose_tf32<<<dim3(C_DIM / 32, FF_DIM / 32), tb>>>(W2, W2T, FF_DIM, C_DIM);

    // QKV: [M,256] @ [256,768]
    mma_gemm<0><<<dim3(QKV_N / 128, M_DIM / 128), 256, GEMM_SMEM>>>(
        h1, Wqkv, nullptr, nullptr, qkv, M_DIM, QKV_N, C_DIM);
    attn_mma_kernel<<<dim3(H_DIM, B_DIM), 256, ATTN_SMEM>>>(qkv, attn);
    // proj + bias + residual(x)
    mma_gemm<3><<<dim3(C_DIM / 128, M_DIM / 128), 256, GEMM_SMEM>>>(
        attn, WpT, bp, x, x1, M_DIM, C_DIM, C_DIM);
    ln_kernel<<<M_DIM, 256>>>(x1, g2, be2, h2);
    // FFN up + GELU
    mma_gemm<2><<<dim3(FF_DIM / 128, M_DIM / 128), 256, GEMM_SMEM>>>(
        h2, W1T, b1, nullptr, ffn1, M_DIM, FF_DIM, C_DIM);
    // FFN down + bias + residual(x1)
    mma_gemm<3><<<dim3(C_DIM / 128, M_DIM / 128), 256, GEMM_SMEM>>>(
        ffn1, W2T, b2, x1, out, M_DIM, C_DIM, FF_DIM);
}

// round 14
// speedup vs baseline: 1.0413x; 1.0001x over previous
#include <cuda_runtime.h>
#include <cuda_bf16.h>
#include <math.h>
#include <stdint.h>

#define C_DIM 256
#define H_DIM 16
#define HS_DIM 16
#define B_DIM 64
#define T_DIM 256
#define M_DIM 16384
#define FF_DIM 1024
#define QKV_N 768
#define LN_EPS 1e-5f

// ---------------- scratch ----------------------------------------------------
__device__ float g_h1[M_DIM * C_DIM];
__device__ float g_qkv[M_DIM * QKV_N];
__device__ float g_attn[M_DIM * C_DIM];
__device__ float g_x1[M_DIM * C_DIM];
__device__ float g_h2[M_DIM * C_DIM];
__device__ float g_ffn1[M_DIM * FF_DIM];
__device__ float g_Wqkv[QKV_N * C_DIM];   // [N,K] K-major
__device__ float g_WpT[C_DIM * C_DIM];
__device__ float g_W1T[FF_DIM * C_DIM];
__device__ float g_W2T[C_DIM * FF_DIM];

// ---------------- helpers ----------------------------------------------------
__device__ __forceinline__ uint32_t smem_u32(const void* p) {
    uint32_t a;
    asm("{ .reg .u64 t; cvta.to.shared.u64 t, %1; cvt.u32.u64 %0, t; }" : "=r"(a) : "l"(p));
    return a;
}
__device__ __forceinline__ float to_tf32(float x) {
    uint32_t u;
    asm("cvt.rna.tf32.f32 %0, %1;" : "=r"(u) : "f"(x));
    return __uint_as_float(u);
}
static __device__ __forceinline__ void cp_async16(uint32_t dst, const void* src) {
    asm volatile("cp.async.cg.shared.global [%0], [%1], 16;" :: "r"(dst), "l"(src) : "memory");
}
#define CP_COMMIT() asm volatile("cp.async.commit_group;" ::: "memory")
template <int N> __device__ __forceinline__ void cp_wait() {
    asm volatile("cp.async.wait_group %0;" :: "n"(N) : "memory");
}

__device__ __forceinline__ void mma_tf32(float* c, uint32_t a0, uint32_t a1,
                                         uint32_t a2, uint32_t a3,
                                         uint32_t b0, uint32_t b1) {
    asm volatile(
        "mma.sync.aligned.m16n8k8.row.col.f32.tf32.tf32.f32 "
        "{%0,%1,%2,%3}, {%4,%5,%6,%7}, {%8,%9}, {%0,%1,%2,%3};"
        : "+f"(c[0]), "+f"(c[1]), "+f"(c[2]), "+f"(c[3])
        : "r"(a0), "r"(a1), "r"(a2), "r"(a3), "r"(b0), "r"(b1));
}

// ---------------- LayerNorm (output pre-rounded to tf32) ---------------------
__global__ void ln_kernel(const float* __restrict__ x, const float* __restrict__ g,
                          const float* __restrict__ b, float* __restrict__ out) {
    int row = blockIdx.x, tid = threadIdx.x;
    float v = x[(size_t)row * C_DIM + tid];
    float s = v, s2 = v * v;
    #pragma unroll
    for (int o = 16; o; o >>= 1) {
        s += __shfl_xor_sync(0xFFFFFFFFu, s, o);
        s2 += __shfl_xor_sync(0xFFFFFFFFu, s2, o);
    }
    __shared__ float ws[8], ws2[8];
    int w = tid >> 5, l = tid & 31;
    if (l == 0) { ws[w] = s; ws2[w] = s2; }
    __syncthreads();
    if (tid < 32) {
        float t1 = (tid < 8) ? ws[tid] : 0.f;
        float t2 = (tid < 8) ? ws2[tid] : 0.f;
        #pragma unroll
        for (int o = 4; o; o >>= 1) {
            t1 += __shfl_xor_sync(0xFFFFFFFFu, t1, o);
            t2 += __shfl_xor_sync(0xFFFFFFFFu, t2, o);
        }
        if (tid == 0) { ws[0] = t1; ws2[0] = t2; }
    }
    __syncthreads();
    float mean = ws[0] * (1.f / C_DIM);
    float var = ws2[0] * (1.f / C_DIM) - mean * mean;
    out[(size_t)row * C_DIM + tid] =
        to_tf32((v - mean) * rsqrtf(var + LN_EPS) * g[tid] + b[tid]);
}

// ---------------- weight repacks ----------------------------------------------
// QKV: [H,C,HS] -> [N,K] K-major; reads are coalesced (d,k fastest = contiguous)
__global__ void repack_qkv(const float* __restrict__ Wq, const float* __restrict__ Wk,
                           const float* __restrict__ Wv) {
    int i = blockIdx.x * blockDim.x + threadIdx.x;
    if (i >= QKV_N * C_DIM) return;
    int n = i >> 8, k = i & 255;
    int sel = n >> 8, nn = n & 255;
    int h = nn >> 4, d = nn & 15;
    int src = h * (C_DIM * HS_DIM) + k * HS_DIM + d;
    const float* W = (sel == 0) ? Wq : (sel == 1) ? Wk : Wv;
    g_Wqkv[i] = to_tf32(W[src]);
}

// coalesced 32x32 smem-tiled transpose: src [rows, cols] -> dst [cols, rows],
// output pre-rounded to tf32. Block 32x8, 4 rows per thread. Replaces the
// fully-uncoalesced repack_rest (strided 4B reads, ~16-32x traffic blowup).
__global__ void transpose_tf32(const float* __restrict__ src, float* __restrict__ dst,
                               int rows, int cols) {
    __shared__ float tile[32][33];
    int bx = blockIdx.x * 32, by = blockIdx.y * 32;
    int tx = threadIdx.x, ty = threadIdx.y;
    #pragma unroll
    for (int j = 0; j < 32; j += 8)
        tile[ty + j][tx] = src[(size_t)(by + ty + j) * cols + bx + tx];
    __syncthreads();
    #pragma unroll
    for (int j = 0; j < 32; j += 8)
        dst[(size_t)(bx + ty + j) * rows + by + tx] = to_tf32(tile[tx][ty + j]);
}

// ---------------- tf32 mma.sync GEMM (R6 config: best measured) --------------
#define TILE_F  (128 * 36)
#define TILE_B  (TILE_F * 4)
#define STAGE_B (2 * TILE_B)
#define GEMM_SMEM (3 * STAGE_B)

__device__ __forceinline__ void load_tile(uint32_t sdst, const float* __restrict__ gp,
                                          int ld, int row0, int kc, int tid) {
    #pragma unroll
    for (int i = 0; i < 4; i++) {
        int f = i * 256 + tid;
        int row = f >> 3;
        int c4 = (f & 7) * 4;
        cp_async16(sdst + (uint32_t)(row * 144 + c4 * 4),
                   gp + (size_t)(row0 + row) * ld + kc + c4);
    }
}

template <int EPI>
__global__ __launch_bounds__(256, 2) void mma_gemm(
    const float* __restrict__ A, const float* __restrict__ Bw,
    const float* __restrict__ bias, const float* __restrict__ resid,
    float* __restrict__ out, int M, int N, int K) {
    extern __shared__ float smem[];
    uint32_t sb = smem_u32(smem);
    int tid = threadIdx.x, wid = tid >> 5, lane = tid & 31;
    int g = lane >> 2, t = lane & 3;
    int warpM = wid & 1, warpN = wid >> 1;
    int mbase = warpM * 64, nbase = warpN * 32;
    int bm = blockIdx.y * 128, bn = blockIdx.x * 128;
    int nc = K >> 5;

    float acc[4][4][4];
    #pragma unroll
    for (int i = 0; i < 4; i++)
        #pragma unroll
        for (int j = 0; j < 4; j++)
            #pragma unroll
            for (int e = 0; e < 4; e++) acc[i][j][e] = 0.f;

    load_tile(sb, A, K, bm, 0, tid);
    load_tile(sb + TILE_B, Bw, K, bn, 0, tid);
    CP_COMMIT();
    load_tile(sb + STAGE_B, A, K, bm, 32, tid);
    load_tile(sb + STAGE_B + TILE_B, Bw, K, bn, 32, tid);
    CP_COMMIT();

    for (int c = 0; c < nc; c++) {
        if (c < nc - 1) cp_wait<1>(); else cp_wait<0>();
        __syncthreads();

        if (c + 2 < nc) {
            uint32_t st = sb + ((c + 2) % 3) * STAGE_B;
            load_tile(st, A, K, bm, (c + 2) << 5, tid);
            load_tile(st + TILE_B, Bw, K, bn, (c + 2) << 5, tid);
            CP_COMMIT();
        }

        const float* sA = smem + (c % 3) * (STAGE_B / 4);
        const float* sB = sA + TILE_F;
        #pragma unroll
        for (int kk = 0; kk < 4; kk++) {
            int k0 = kk * 8 + t;
            uint32_t bf[4][2];
            #pragma unroll
            for (int nt = 0; nt < 4; nt++) {
                int rn = nbase + nt * 8 + g;
                bf[nt][0] = __float_as_uint(sB[rn * 36 + k0]);
                bf[nt][1] = __float_as_uint(sB[rn * 36 + k0 + 4]);
            }
            #pragma unroll
            for (int mt = 0; mt < 4; mt++) {
                int r0 = mbase + mt * 16 + g;
                uint32_t a0 = __float_as_uint(sA[r0 * 36 + k0]);
                uint32_t a1 = __float_as_uint(sA[(r0 + 8) * 36 + k0]);
                uint32_t a2 = __float_as_uint(sA[r0 * 36 + k0 + 4]);
                uint32_t a3 = __float_as_uint(sA[(r0 + 8) * 36 + k0 + 4]);
                #pragma unroll
                for (int nt = 0; nt < 4; nt++)
                    mma_tf32(acc[mt][nt], a0, a1, a2, a3, bf[nt][0], bf[nt][1]);
            }
        }
    }

    #pragma unroll
    for (int mt = 0; mt < 4; mt++) {
        int row = bm + mbase + mt * 16 + g;
        #pragma unroll
        for (int nt = 0; nt < 4; nt++) {
            int col = bn + nbase + nt * 8 + 2 * t;
            float2 v0 = make_float2(acc[mt][nt][0], acc[mt][nt][1]);
            float2 v1 = make_float2(acc[mt][nt][2], acc[mt][nt][3]);
            if (EPI >= 2) {
                float2 bv = *(const float2*)&bias[col];
                v0.x += bv.x; v0.y += bv.y; v1.x += bv.x; v1.y += bv.y;
            }
            if (EPI == 2) {
                v0.x = to_tf32(0.5f * v0.x * (1.f + erff(v0.x * 0.70710678118654752f)));
                v0.y = to_tf32(0.5f * v0.y * (1.f + erff(v0.y * 0.70710678118654752f)));
                v1.x = to_tf32(0.5f * v1.x * (1.f + erff(v1.x * 0.70710678118654752f)));
                v1.y = to_tf32(0.5f * v1.y * (1.f + erff(v1.y * 0.70710678118654752f)));
            }
            if (EPI == 3) {
                float2 r0 = *(const float2*)&resid[(size_t)row * N + col];
                float2 r1 = *(const float2*)&resid[(size_t)(row + 8) * N + col];
                v0.x += r0.x; v0.y += r0.y; v1.x += r1.x; v1.y += r1.y;
            }
            *(float2*)&out[(size_t)row * N + col] = v0;
            *(float2*)&out[(size_t)(row + 8) * N + col] = v1;
        }
    }
}

// ---------------- tensor-core flash attention (R6, unchanged) ----------------
#define QKV_PAD 18
#define P_PAD 66
#define SQ_OFF 0
#define SK_OFF (256 * QKV_PAD)
#define SV_OFF (512 * QKV_PAD)
#define SP_OFF (768 * QKV_PAD)
#define ATTN_SMEM ((768 * QKV_PAD + 8 * 16 * P_PAD) * 4)

__global__ __launch_bounds__(256) void attn_mma_kernel(const float* __restrict__ qkv,
                                                       float* __restrict__ out) {
    extern __shared__ float sm[];
    float* sQ = sm + SQ_OFF;
    float* sK = sm + SK_OFF;
    float* sV = sm + SV_OFF;
    int h = blockIdx.x, b = blockIdx.y;
    int tid = threadIdx.x, w = tid >> 5, lane = tid & 31;
    int g = lane >> 2, t = lane & 3;
    float* sP = sm + SP_OFF + w * (16 * P_PAD);

    {
        const float* rp = qkv + (size_t)(b * T_DIM + tid) * QKV_N + h * 16;
        #pragma unroll
        for (int d = 0; d < 16; d += 4) {
            float4 q4 = *(const float4*)&rp[d];
            sQ[tid * QKV_PAD + d]     = to_tf32(q4.x * 0.0625f);
            sQ[tid * QKV_PAD + d + 1] = to_tf32(q4.y * 0.0625f);
            sQ[tid * QKV_PAD + d + 2] = to_tf32(q4.z * 0.0625f);
            sQ[tid * QKV_PAD + d + 3] = to_tf32(q4.w * 0.0625f);
            float4 k4 = *(const float4*)&rp[256 + d];
            sK[tid * QKV_PAD + d]     = to_tf32(k4.x);
            sK[tid * QKV_PAD + d + 1] = to_tf32(k4.y);
            sK[tid * QKV_PAD + d + 2] = to_tf32(k4.z);
            sK[tid * QKV_PAD + d + 3] = to_tf32(k4.w);
            float4 v4 = *(const float4*)&rp[512 + d];
            sV[tid * QKV_PAD + d]     = to_tf32(v4.x);
            sV[tid * QKV_PAD + d + 1] = to_tf32(v4.y);
            sV[tid * QKV_PAD + d + 2] = to_tf32(v4.z);
            sV[tid * QKV_PAD + d + 3] = to_tf32(v4.w);
        }
    }
    __syncthreads();

    #pragma unroll
    for (int half = 0; half < 2; half++) {
        int rt = half ? (15 - w) : w;
        int r0 = rt * 16;
        int nkt = (rt >> 2) + 1;
        float m0 = -1e30f, m1 = -1e30f, l0 = 0.f, l1 = 0.f;
        float o[2][4] = {};

        for (int kt = 0; kt < nkt; kt++) {
            int kb = kt * 64;
            float s[8][4];
            #pragma unroll
            for (int nt = 0; nt < 8; nt++) {
                s[nt][0] = 0.f; s[nt][1] = 0.f; s[nt][2] = 0.f; s[nt][3] = 0.f;
            }
            #pragma unroll
            for (int ks = 0; ks < 2; ks++) {
                int k0 = ks * 8 + t;
                uint32_t a0 = __float_as_uint(sQ[(r0 + g) * QKV_PAD + k0]);
                uint32_t a1 = __float_as_uint(sQ[(r0 + g + 8) * QKV_PAD + k0]);
                uint32_t a2 = __float_as_uint(sQ[(r0 + g) * QKV_PAD + k0 + 4]);
                uint32_t a3 = __float_as_uint(sQ[(r0 + g + 8) * QKV_PAD + k0 + 4]);
                #pragma unroll
                for (int nt = 0; nt < 8; nt++) {
                    int rn = kb + nt * 8 + g;
                    uint32_t b0 = __float_as_uint(sK[rn * QKV_PAD + k0]);
                    uint32_t b1 = __float_as_uint(sK[rn * QKV_PAD + k0 + 4]);
                    mma_tf32(s[nt], a0, a1, a2, a3, b0, b1);
                }
            }
            if (kt == nkt - 1) {
                int rlo = r0 + g, rhi = r0 + g + 8;
                #pragma unroll
                for (int nt = 0; nt < 8; nt++) {
                    int c0 = kb + nt * 8 + 2 * t;
                    if (c0 > rlo) s[nt][0] = -1e30f;
                    if (c0 + 1 > rlo) s[nt][1] = -1e30f;
                    if (c0 > rhi) s[nt][2] = -1e30f;
                    if (c0 + 1 > rhi) s[nt][3] = -1e30f;
                }
            }
            float rm0 = -1e30f, rm1 = -1e30f;
            #pragma unroll
            for (int nt = 0; nt < 8; nt++) {
                rm0 = fmaxf(rm0, fmaxf(s[nt][0], s[nt][1]));
                rm1 = fmaxf(rm1, fmaxf(s[nt][2], s[nt][3]));
            }
            rm0 = fmaxf(rm0, __shfl_xor_sync(0xFFFFFFFFu, rm0, 1));
            rm0 = fmaxf(rm0, __shfl_xor_sync(0xFFFFFFFFu, rm0, 2));
            rm1 = fmaxf(rm1, __shfl_xor_sync(0xFFFFFFFFu, rm1, 1));
            rm1 = fmaxf(rm1, __shfl_xor_sync(0xFFFFFFFFu, rm1, 2));
            float mn0 = fmaxf(m0, rm0), mn1 = fmaxf(m1, rm1);
            float cf0 = __expf(m0 - mn0), cf1 = __expf(m1 - mn1);
            m0 = mn0; m1 = mn1;
            l0 *= cf0; l1 *= cf1;
            o[0][0] *= cf0; o[0][1] *= cf0; o[1][0] *= cf0; o[1][1] *= cf0;
            o[0][2] *= cf1; o[0][3] *= cf1; o[1][2] *= cf1; o[1][3] *= cf1;

            float ps0 = 0.f, ps1 = 0.f;
            #pragma unroll
            for (int nt = 0; nt < 8; nt++) {
                float p0 = __expf(s[nt][0] - m0);
                float p1 = __expf(s[nt][1] - m0);
                float p2 = __expf(s[nt][2] - m1);
                float p3 = __expf(s[nt][3] - m1);
                ps0 += p0 + p1; ps1 += p2 + p3;
                int cc = nt * 8 + 2 * t;
                sP[g * P_PAD + cc] = to_tf32(p0);
                sP[g * P_PAD + cc + 1] = to_tf32(p1);
                sP[(g + 8) * P_PAD + cc] = to_tf32(p2);
                sP[(g + 8) * P_PAD + cc + 1] = to_tf32(p3);
            }
            ps0 += __shfl_xor_sync(0xFFFFFFFFu, ps0, 1);
            ps0 += __shfl_xor_sync(0xFFFFFFFFu, ps0, 2);
            ps1 += __shfl_xor_sync(0xFFFFFFFFu, ps1, 1);
            ps1 += __shfl_xor_sync(0xFFFFFFFFu, ps1, 2);
            l0 += ps0; l1 += ps1;
            __syncwarp();

            #pragma unroll
            for (int ks = 0; ks < 8; ks++) {
                int k0 = ks * 8 + t;
                uint32_t a0 = __float_as_uint(sP[g * P_PAD + k0]);
                uint32_t a1 = __float_as_uint(sP[(g + 8) * P_PAD + k0]);
                uint32_t a2 = __float_as_uint(sP[g * P_PAD + k0 + 4]);
                uint32_t a3 = __float_as_uint(sP[(g + 8) * P_PAD + k0 + 4]);
                #pragma unroll
                for (int nt2 = 0; nt2 < 2; nt2++) {
                    uint32_t b0 = __float_as_uint(sV[(kb + k0) * QKV_PAD + nt2 * 8 + g]);
                    uint32_t b1 = __float_as_uint(sV[(kb + k0 + 4) * QKV_PAD + nt2 * 8 + g]);
                    mma_tf32(o[nt2], a0, a1, a2, a3, b0, b1);
                }
            }
            __syncwarp();
        }

        float i0 = 1.f / l0, i1 = 1.f / l1;
        #pragma unroll
        for (int nt2 = 0; nt2 < 2; nt2++) {
            int col = h * 16 + nt2 * 8 + 2 * t;
            float2 v0 = make_float2(to_tf32(o[nt2][0] * i0), to_tf32(o[nt2][1] * i0));
            float2 v1 = make_float2(to_tf32(o[nt2][2] * i1), to_tf32(o[nt2][3] * i1));
            *(float2*)&out[(size_t)(b * T_DIM + r0 + g) * C_DIM + col] = v0;
            *(float2*)&out[(size_t)(b * T_DIM + r0 + g + 8) * C_DIM + col] = v1;
        }
    }
}

// ---------------- launch -----------------------------------------------------
extern "C" void kernel_launch(void* const* d_in, const int* in_sizes, int n_in,
                              void* d_out, int out_size) {
    const float* x = (const float*)d_in[0];
    const float* Wq = (const float*)d_in[1];
    const float* Wk = (const float*)d_in[2];
    const float* Wv = (const float*)d_in[3];
    const float* Wp = (const float*)d_in[4];
    const float* bp = (const float*)d_in[5];
    const float* W1 = (const float*)d_in[6];
    const float* b1 = (const float*)d_in[7];
    const float* W2 = (const float*)d_in[8];
    const float* b2 = (const float*)d_in[9];
    const float* g1 = (const float*)d_in[10];
    const float* be1 = (const float*)d_in[11];
    const float* g2 = (const float*)d_in[12];
    const float* be2 = (const float*)d_in[13];
    float* out = (float*)d_out;

    float *h1, *qkv, *attn, *x1, *h2, *ffn1, *Wqkv, *WpT, *W1T, *W2T;
    cudaGetSymbolAddress((void**)&h1, g_h1);
    cudaGetSymbolAddress((void**)&qkv, g_qkv);
    cudaGetSymbolAddress((void**)&attn, g_attn);
    cudaGetSymbolAddress((void**)&x1, g_x1);
    cudaGetSymbolAddress((void**)&h2, g_h2);
    cudaGetSymbolAddress((void**)&ffn1, g_ffn1);
    cudaGetSymbolAddress((void**)&Wqkv, g_Wqkv);
    cudaGetSymbolAddress((void**)&WpT, g_WpT);
    cudaGetSymbolAddress((void**)&W1T, g_W1T);
    cudaGetSymbolAddress((void**)&W2T, g_W2T);

    cudaFuncSetAttribute(mma_gemm<0>, cudaFuncAttributeMaxDynamicSharedMemorySize, GEMM_SMEM);
    cudaFuncSetAttribute(mma_gemm<2>, cudaFuncAttributeMaxDynamicSharedMemorySize, GEMM_SMEM);
    cudaFuncSetAttribute(mma_gemm<3>, cudaFuncAttributeMaxDynamicSharedMemorySize, GEMM_SMEM);
    cudaFuncSetAttribute(attn_mma_kernel, cudaFuncAttributeMaxDynamicSharedMemorySize, ATTN_SMEM);

    ln_kernel<<<M_DIM, 256>>>(x, g1, be1, h1);
    repack_qkv<<<(QKV_N * C_DIM + 255) / 256, 256>>>(Wq, Wk, Wv);
    // coalesced tiled transposes (replaces uncoalesced repack_rest):
    dim3 tb(32, 8);
    transpose_tf32<<<dim3(C_DIM / 32, C_DIM / 32), tb>>>(Wp, WpT, C_DIM, C_DIM);
    transpose_tf32<<<dim3(FF_DIM / 32, C_DIM / 32), tb>>>(W1, W1T, C_DIM, FF_DIM);
    transpose_tf32<<<dim3(C_DIM / 32, FF_DIM / 32), tb>>>(W2, W2T, FF_DIM, C_DIM);

    // QKV: [M,256] @ [256,768]
    mma_gemm<0><<<dim3(QKV_N / 128, M_DIM / 128), 256, GEMM_SMEM>>>(
        h1, Wqkv, nullptr, nullptr, qkv, M_DIM, QKV_N, C_DIM);
    attn_mma_kernel<<<dim3(H_DIM, B_DIM), 256, ATTN_SMEM>>>(qkv, attn);
    // proj + bias + residual(x)
    mma_gemm<3><<<dim3(C_DIM / 128, M_DIM / 128), 256, GEMM_SMEM>>>(
        attn, WpT, bp, x, x1, M_DIM, C_DIM, C_DIM);
    ln_kernel<<<M_DIM, 256>>>(x1, g2, be2, h2);
    // FFN up + GELU
    mma_gemm<2><<<dim3(FF_DIM / 128, M_DIM / 128), 256, GEMM_SMEM>>>(
        h2, W1T, b1, nullptr, ffn1, M_DIM, FF_DIM, C_DIM);
    // FFN down + bias + residual(x1)
    mma_gemm<3><<<dim3(C_DIM / 128, M_DIM / 128), 256, GEMM_SMEM>>>(
        ffn1, W2T, b2, x1, out, M_DIM, C_DIM, FF_DIM);
}

// round 15
// speedup vs baseline: 1.1721x; 1.1256x over previous
#include <cuda_runtime.h>
#include <cuda_fp16.h>
#include <math.h>
#include <stdint.h>

#define C_DIM 256
#define H_DIM 16
#define HS_DIM 16
#define B_DIM 64
#define T_DIM 256
#define M_DIM 16384
#define FF_DIM 1024
#define QKV_N 768
#define LN_EPS 1e-5f

// ---------------- scratch (half activations/weights; fp32 residual stream) ---
__device__ __half g_h1[M_DIM * C_DIM];
__device__ __half g_qkv[M_DIM * QKV_N];
__device__ __half g_attn[M_DIM * C_DIM];
__device__ float  g_x1[M_DIM * C_DIM];
__device__ __half g_h2[M_DIM * C_DIM];
__device__ __half g_ffn1[M_DIM * FF_DIM];
__device__ __half g_Wqkv[QKV_N * C_DIM];   // [N,K] K-major
__device__ __half g_WpT[C_DIM * C_DIM];
__device__ __half g_W1T[FF_DIM * C_DIM];
__device__ __half g_W2T[C_DIM * FF_DIM];

// ---------------- helpers ----------------------------------------------------
__device__ __forceinline__ uint32_t smem_u32(const void* p) {
    uint32_t a;
    asm("{ .reg .u64 t; cvta.to.shared.u64 t, %1; cvt.u32.u64 %0, t; }" : "=r"(a) : "l"(p));
    return a;
}
__device__ __forceinline__ float to_tf32(float x) {
    uint32_t u;
    asm("cvt.rna.tf32.f32 %0, %1;" : "=r"(u) : "f"(x));
    return __uint_as_float(u);
}
static __device__ __forceinline__ void cp_async16(uint32_t dst, const void* src) {
    asm volatile("cp.async.cg.shared.global [%0], [%1], 16;" :: "r"(dst), "l"(src) : "memory");
}
#define CP_COMMIT() asm volatile("cp.async.commit_group;" ::: "memory")
template <int N> __device__ __forceinline__ void cp_wait() {
    asm volatile("cp.async.wait_group %0;" :: "n"(N) : "memory");
}

// fp16 mma m16n8k16, fp32 accum (2x MACs/instr vs tf32 k8)
__device__ __forceinline__ void mma_f16(float* c, uint32_t a0, uint32_t a1,
                                        uint32_t a2, uint32_t a3,
                                        uint32_t b0, uint32_t b1) {
    asm volatile(
        "mma.sync.aligned.m16n8k16.row.col.f32.f16.f16.f32 "
        "{%0,%1,%2,%3}, {%4,%5,%6,%7}, {%8,%9}, {%0,%1,%2,%3};"
        : "+f"(c[0]), "+f"(c[1]), "+f"(c[2]), "+f"(c[3])
        : "r"(a0), "r"(a1), "r"(a2), "r"(a3), "r"(b0), "r"(b1));
}
// tf32 mma (attention only)
__device__ __forceinline__ void mma_tf32(float* c, uint32_t a0, uint32_t a1,
                                         uint32_t a2, uint32_t a3,
                                         uint32_t b0, uint32_t b1) {
    asm volatile(
        "mma.sync.aligned.m16n8k8.row.col.f32.tf32.tf32.f32 "
        "{%0,%1,%2,%3}, {%4,%5,%6,%7}, {%8,%9}, {%0,%1,%2,%3};"
        : "+f"(c[0]), "+f"(c[1]), "+f"(c[2]), "+f"(c[3])
        : "r"(a0), "r"(a1), "r"(a2), "r"(a3), "r"(b0), "r"(b1));
}

__device__ __forceinline__ void store2(float* out, size_t idx, float x, float y) {
    *(float2*)&out[idx] = make_float2(x, y);
}
__device__ __forceinline__ void store2(__half* out, size_t idx, float x, float y) {
    *(__half2*)&out[idx] = __floats2half2_rn(x, y);
}

// ---------------- LayerNorm (fp32 in, half out) ------------------------------
__global__ void ln_kernel(const float* __restrict__ x, const float* __restrict__ g,
                          const float* __restrict__ b, __half* __restrict__ out) {
    int row = blockIdx.x, tid = threadIdx.x;
    float v = x[(size_t)row * C_DIM + tid];
    float s = v, s2 = v * v;
    #pragma unroll
    for (int o = 16; o; o >>= 1) {
        s += __shfl_xor_sync(0xFFFFFFFFu, s, o);
        s2 += __shfl_xor_sync(0xFFFFFFFFu, s2, o);
    }
    __shared__ float ws[8], ws2[8];
    int w = tid >> 5, l = tid & 31;
    if (l == 0) { ws[w] = s; ws2[w] = s2; }
    __syncthreads();
    if (tid < 32) {
        float t1 = (tid < 8) ? ws[tid] : 0.f;
        float t2 = (tid < 8) ? ws2[tid] : 0.f;
        #pragma unroll
        for (int o = 4; o; o >>= 1) {
            t1 += __shfl_xor_sync(0xFFFFFFFFu, t1, o);
            t2 += __shfl_xor_sync(0xFFFFFFFFu, t2, o);
        }
        if (tid == 0) { ws[0] = t1; ws2[0] = t2; }
    }
    __syncthreads();
    float mean = ws[0] * (1.f / C_DIM);
    float var = ws2[0] * (1.f / C_DIM) - mean * mean;
    out[(size_t)row * C_DIM + tid] =
        __float2half_rn((v - mean) * rsqrtf(var + LN_EPS) * g[tid] + b[tid]);
}

// ---------------- weight repacks ---------------------------------------------
__global__ void repack_qkv(const float* __restrict__ Wq, const float* __restrict__ Wk,
                           const float* __restrict__ Wv) {
    int i = blockIdx.x * blockDim.x + threadIdx.x;
    if (i >= QKV_N * C_DIM) return;
    int n = i >> 8, k = i & 255;
    int sel = n >> 8, nn = n & 255;
    int h = nn >> 4, d = nn & 15;
    int src = h * (C_DIM * HS_DIM) + k * HS_DIM + d;
    const float* W = (sel == 0) ? Wq : (sel == 1) ? Wk : Wv;
    g_Wqkv[i] = __float2half_rn(W[src]);
}

__global__ void transpose_f16(const float* __restrict__ src, __half* __restrict__ dst,
                              int rows, int cols) {
    __shared__ float tile[32][33];
    int bx = blockIdx.x * 32, by = blockIdx.y * 32;
    int tx = threadIdx.x, ty = threadIdx.y;
    #pragma unroll
    for (int j = 0; j < 32; j += 8)
        tile[ty + j][tx] = src[(size_t)(by + ty + j) * cols + bx + tx];
    __syncthreads();
    #pragma unroll
    for (int j = 0; j < 32; j += 8)
        dst[(size_t)(bx + ty + j) * rows + by + tx] = __float2half_rn(tile[tx][ty + j]);
}

// ---------------- fp16 mma.sync GEMM (R6 skeleton, half operands) ------------
// CTA 128x128, BK=32 elems, 256 thr = 8 warps (2M x 4N), warp tile 64x32.
// smem tile: 128 rows x 40 halfs (80 B; 16B-aligned rows; word pattern g*20+t
// conflict-free). 3-stage ring, one __syncthreads per chunk.
#define PAD_H  40
#define TILE_B (128 * PAD_H * 2)    // 10240 B
#define STAGE_B (2 * TILE_B)        // 20480 B
#define GEMM_SMEM (3 * STAGE_B)     // 61440 B -> 2 CTA/SM

__device__ __forceinline__ void load_tile(uint32_t sdst, const __half* __restrict__ gp,
                                          int ld, int row0, int kc, int tid) {
    #pragma unroll
    for (int i = 0; i < 2; i++) {
        int f = i * 256 + tid;       // 16B-chunk index over 128 rows x 4 segs
        int row = f >> 2;
        int seg = f & 3;             // 8 halfs per seg
        cp_async16(sdst + (uint32_t)(row * 80 + seg * 16),
                   gp + (size_t)(row0 + row) * ld + kc + seg * 8);
    }
}

// EPI: 0 none (half out), 2 bias+GELU (half out), 3 bias+residual (float out)
template <int EPI, typename OutT>
__global__ __launch_bounds__(256, 2) void mma_gemm(
    const __half* __restrict__ A, const __half* __restrict__ Bw,
    const float* __restrict__ bias, const float* __restrict__ resid,
    OutT* __restrict__ out, int M, int N, int K) {
    extern __shared__ __half smem[];
    uint32_t sb = smem_u32(smem);
    int tid = threadIdx.x, wid = tid >> 5, lane = tid & 31;
    int g = lane >> 2, t = lane & 3;
    int warpM = wid & 1, warpN = wid >> 1;
    int mbase = warpM * 64, nbase = warpN * 32;
    int bm = blockIdx.y * 128, bn = blockIdx.x * 128;
    int nc = K >> 5;

    float acc[4][4][4];
    #pragma unroll
    for (int i = 0; i < 4; i++)
        #pragma unroll
        for (int j = 0; j < 4; j++)
            #pragma unroll
            for (int e = 0; e < 4; e++) acc[i][j][e] = 0.f;

    load_tile(sb, A, K, bm, 0, tid);
    load_tile(sb + TILE_B, Bw, K, bn, 0, tid);
    CP_COMMIT();
    load_tile(sb + STAGE_B, A, K, bm, 32, tid);
    load_tile(sb + STAGE_B + TILE_B, Bw, K, bn, 32, tid);
    CP_COMMIT();

    for (int c = 0; c < nc; c++) {
        if (c < nc - 1) cp_wait<1>(); else cp_wait<0>();
        __syncthreads();

        if (c + 2 < nc) {
            uint32_t st = sb + ((c + 2) % 3) * STAGE_B;
            load_tile(st, A, K, bm, (c + 2) << 5, tid);
            load_tile(st + TILE_B, Bw, K, bn, (c + 2) << 5, tid);
            CP_COMMIT();
        }

        const __half* sA = smem + (size_t)(c % 3) * (STAGE_B / 2);
        const __half* sB = sA + 128 * PAD_H;
        // 2 k16 steps per 32-elem chunk
        #pragma unroll
        for (int kk = 0; kk < 2; kk++) {
            int k0 = kk * 16 + 2 * t;          // half index of first of the pair
            uint32_t bf[4][2];
            #pragma unroll
            for (int nt = 0; nt < 4; nt++) {
                int rn = nbase + nt * 8 + g;
                bf[nt][0] = *(const uint32_t*)&sB[rn * PAD_H + k0];
                bf[nt][1] = *(const uint32_t*)&sB[rn * PAD_H + k0 + 8];
            }
            #pragma unroll
            for (int mt = 0; mt < 4; mt++) {
                int r0 = mbase + mt * 16 + g;
                uint32_t a0 = *(const uint32_t*)&sA[r0 * PAD_H + k0];
                uint32_t a1 = *(const uint32_t*)&sA[(r0 + 8) * PAD_H + k0];
                uint32_t a2 = *(const uint32_t*)&sA[r0 * PAD_H + k0 + 8];
                uint32_t a3 = *(const uint32_t*)&sA[(r0 + 8) * PAD_H + k0 + 8];
                #pragma unroll
                for (int nt = 0; nt < 4; nt++)
                    mma_f16(acc[mt][nt], a0, a1, a2, a3, bf[nt][0], bf[nt][1]);
            }
        }
    }

    #pragma unroll
    for (int mt = 0; mt < 4; mt++) {
        int row = bm + mbase + mt * 16 + g;
        #pragma unroll
        for (int nt = 0; nt < 4; nt++) {
            int col = bn + nbase + nt * 8 + 2 * t;
            float v0x = acc[mt][nt][0], v0y = acc[mt][nt][1];
            float v1x = acc[mt][nt][2], v1y = acc[mt][nt][3];
            if (EPI >= 2) {
                float2 bv = *(const float2*)&bias[col];
                v0x += bv.x; v0y += bv.y; v1x += bv.x; v1y += bv.y;
            }
            if (EPI == 2) {
                v0x = 0.5f * v0x * (1.f + erff(v0x * 0.70710678118654752f));
                v0y = 0.5f * v0y * (1.f + erff(v0y * 0.70710678118654752f));
                v1x = 0.5f * v1x * (1.f + erff(v1x * 0.70710678118654752f));
                v1y = 0.5f * v1y * (1.f + erff(v1y * 0.70710678118654752f));
            }
            if (EPI == 3) {
                float2 r0 = *(const float2*)&resid[(size_t)row * N + col];
                float2 r1 = *(const float2*)&resid[(size_t)(row + 8) * N + col];
                v0x += r0.x; v0y += r0.y; v1x += r1.x; v1y += r1.y;
            }
            store2(out, (size_t)row * N + col, v0x, v0y);
            store2(out, (size_t)(row + 8) * N + col, v1x, v1y);
        }
    }
}

// ---------------- tensor-core flash attention (tf32 core; half in/out) -------
#define QKV_PAD 18
#define P_PAD 66
#define SQ_OFF 0
#define SK_OFF (256 * QKV_PAD)
#define SV_OFF (512 * QKV_PAD)
#define SP_OFF (768 * QKV_PAD)
#define ATTN_SMEM ((768 * QKV_PAD + 8 * 16 * P_PAD) * 4)

__global__ __launch_bounds__(256) void attn_mma_kernel(const __half* __restrict__ qkv,
                                                       __half* __restrict__ out) {
    extern __shared__ float sm[];
    float* sQ = sm + SQ_OFF;
    float* sK = sm + SK_OFF;
    float* sV = sm + SV_OFF;
    int h = blockIdx.x, b = blockIdx.y;
    int tid = threadIdx.x, w = tid >> 5, lane = tid & 31;
    int g = lane >> 2, t = lane & 3;
    float* sP = sm + SP_OFF + w * (16 * P_PAD);

    {
        const __half* rp = qkv + (size_t)(b * T_DIM + tid) * QKV_N + h * 16;
        #pragma unroll
        for (int d = 0; d < 16; d++) {
            sQ[tid * QKV_PAD + d] = __half2float(rp[d]) * 0.0625f;  // exact: half*2^-4
            sK[tid * QKV_PAD + d] = __half2float(rp[256 + d]);
            sV[tid * QKV_PAD + d] = __half2float(rp[512 + d]);
        }
    }
    __syncthreads();

    #pragma unroll
    for (int half_i = 0; half_i < 2; half_i++) {
        int rt = half_i ? (15 - w) : w;
        int r0 = rt * 16;
        int nkt = (rt >> 2) + 1;
        float m0 = -1e30f, m1 = -1e30f, l0 = 0.f, l1 = 0.f;
        float o[2][4] = {};

        for (int kt = 0; kt < nkt; kt++) {
            int kb = kt * 64;
            float s[8][4];
            #pragma unroll
            for (int nt = 0; nt < 8; nt++) {
                s[nt][0] = 0.f; s[nt][1] = 0.f; s[nt][2] = 0.f; s[nt][3] = 0.f;
            }
            #pragma unroll
            for (int ks = 0; ks < 2; ks++) {
                int k0 = ks * 8 + t;
                uint32_t a0 = __float_as_uint(sQ[(r0 + g) * QKV_PAD + k0]);
                uint32_t a1 = __float_as_uint(sQ[(r0 + g + 8) * QKV_PAD + k0]);
                uint32_t a2 = __float_as_uint(sQ[(r0 + g) * QKV_PAD + k0 + 4]);
                uint32_t a3 = __float_as_uint(sQ[(r0 + g + 8) * QKV_PAD + k0 + 4]);
                #pragma unroll
                for (int nt = 0; nt < 8; nt++) {
                    int rn = kb + nt * 8 + g;
                    uint32_t b0 = __float_as_uint(sK[rn * QKV_PAD + k0]);
                    uint32_t b1 = __float_as_uint(sK[rn * QKV_PAD + k0 + 4]);
                    mma_tf32(s[nt], a0, a1, a2, a3, b0, b1);
                }
            }
            if (kt == nkt - 1) {
                int rlo = r0 + g, rhi = r0 + g + 8;
                #pragma unroll
                for (int nt = 0; nt < 8; nt++) {
                    int c0 = kb + nt * 8 + 2 * t;
                    if (c0 > rlo) s[nt][0] = -1e30f;
                    if (c0 + 1 > rlo) s[nt][1] = -1e30f;
                    if (c0 > rhi) s[nt][2] = -1e30f;
                    if (c0 + 1 > rhi) s[nt][3] = -1e30f;
                }
            }
            float rm0 = -1e30f, rm1 = -1e30f;
            #pragma unroll
            for (int nt = 0; nt < 8; nt++) {
                rm0 = fmaxf(rm0, fmaxf(s[nt][0], s[nt][1]));
                rm1 = fmaxf(rm1, fmaxf(s[nt][2], s[nt][3]));
            }
            rm0 = fmaxf(rm0, __shfl_xor_sync(0xFFFFFFFFu, rm0, 1));
            rm0 = fmaxf(rm0, __shfl_xor_sync(0xFFFFFFFFu, rm0, 2));
            rm1 = fmaxf(rm1, __shfl_xor_sync(0xFFFFFFFFu, rm1, 1));
            rm1 = fmaxf(rm1, __shfl_xor_sync(0xFFFFFFFFu, rm1, 2));
            float mn0 = fmaxf(m0, rm0), mn1 = fmaxf(m1, rm1);
            float cf0 = __expf(m0 - mn0), cf1 = __expf(m1 - mn1);
            m0 = mn0; m1 = mn1;
            l0 *= cf0; l1 *= cf1;
            o[0][0] *= cf0; o[0][1] *= cf0; o[1][0] *= cf0; o[1][1] *= cf0;
            o[0][2] *= cf1; o[0][3] *= cf1; o[1][2] *= cf1; o[1][3] *= cf1;

            float ps0 = 0.f, ps1 = 0.f;
            #pragma unroll
            for (int nt = 0; nt < 8; nt++) {
                float p0 = __expf(s[nt][0] - m0);
                float p1 = __expf(s[nt][1] - m0);
                float p2 = __expf(s[nt][2] - m1);
                float p3 = __expf(s[nt][3] - m1);
                ps0 += p0 + p1; ps1 += p2 + p3;
                int cc = nt * 8 + 2 * t;
                sP[g * P_PAD + cc] = to_tf32(p0);
                sP[g * P_PAD + cc + 1] = to_tf32(p1);
                sP[(g + 8) * P_PAD + cc] = to_tf32(p2);
                sP[(g + 8) * P_PAD + cc + 1] = to_tf32(p3);
            }
            ps0 += __shfl_xor_sync(0xFFFFFFFFu, ps0, 1);
            ps0 += __shfl_xor_sync(0xFFFFFFFFu, ps0, 2);
            ps1 += __shfl_xor_sync(0xFFFFFFFFu, ps1, 1);
            ps1 += __shfl_xor_sync(0xFFFFFFFFu, ps1, 2);
            l0 += ps0; l1 += ps1;
            __syncwarp();

            #pragma unroll
            for (int ks = 0; ks < 8; ks++) {
                int k0 = ks * 8 + t;
                uint32_t a0 = __float_as_uint(sP[g * P_PAD + k0]);
                uint32_t a1 = __float_as_uint(sP[(g + 8) * P_PAD + k0]);
                uint32_t a2 = __float_as_uint(sP[g * P_PAD + k0 + 4]);
                uint32_t a3 = __float_as_uint(sP[(g + 8) * P_PAD + k0 + 4]);
                #pragma unroll
                for (int nt2 = 0; nt2 < 2; nt2++) {
                    uint32_t b0 = __float_as_uint(sV[(kb + k0) * QKV_PAD + nt2 * 8 + g]);
                    uint32_t b1 = __float_as_uint(sV[(kb + k0 + 4) * QKV_PAD + nt2 * 8 + g]);
                    mma_tf32(o[nt2], a0, a1, a2, a3, b0, b1);
                }
            }
            __syncwarp();
        }

        float i0 = 1.f / l0, i1 = 1.f / l1;
        #pragma unroll
        for (int nt2 = 0; nt2 < 2; nt2++) {
            int col = h * 16 + nt2 * 8 + 2 * t;
            *(__half2*)&out[(size_t)(b * T_DIM + r0 + g) * C_DIM + col] =
                __floats2half2_rn(o[nt2][0] * i0, o[nt2][1] * i0);
            *(__half2*)&out[(size_t)(b * T_DIM + r0 + g + 8) * C_DIM + col] =
                __floats2half2_rn(o[nt2][2] * i1, o[nt2][3] * i1);
        }
    }
}

// ---------------- launch -----------------------------------------------------
extern "C" void kernel_launch(void* const* d_in, const int* in_sizes, int n_in,
                              void* d_out, int out_size) {
    const float* x = (const float*)d_in[0];
    const float* Wq = (const float*)d_in[1];
    const float* Wk = (const float*)d_in[2];
    const float* Wv = (const float*)d_in[3];
    const float* Wp = (const float*)d_in[4];
    const float* bp = (const float*)d_in[5];
    const float* W1 = (const float*)d_in[6];
    const float* b1 = (const float*)d_in[7];
    const float* W2 = (const float*)d_in[8];
    const float* b2 = (const float*)d_in[9];
    const float* g1 = (const float*)d_in[10];
    const float* be1 = (const float*)d_in[11];
    const float* g2 = (const float*)d_in[12];
    const float* be2 = (const float*)d_in[13];
    float* out = (float*)d_out;

    __half *h1, *qkv, *attn, *h2, *ffn1, *Wqkv, *WpT, *W1T, *W2T;
    float* x1;
    cudaGetSymbolAddress((void**)&h1, g_h1);
    cudaGetSymbolAddress((void**)&qkv, g_qkv);
    cudaGetSymbolAddress((void**)&attn, g_attn);
    cudaGetSymbolAddress((void**)&x1, g_x1);
    cudaGetSymbolAddress((void**)&h2, g_h2);
    cudaGetSymbolAddress((void**)&ffn1, g_ffn1);
    cudaGetSymbolAddress((void**)&Wqkv, g_Wqkv);
    cudaGetSymbolAddress((void**)&WpT, g_WpT);
    cudaGetSymbolAddress((void**)&W1T, g_W1T);
    cudaGetSymbolAddress((void**)&W2T, g_W2T);

    cudaFuncSetAttribute((const void*)mma_gemm<0, __half>, cudaFuncAttributeMaxDynamicSharedMemorySize, GEMM_SMEM);
    cudaFuncSetAttribute((const void*)mma_gemm<2, __half>, cudaFuncAttributeMaxDynamicSharedMemorySize, GEMM_SMEM);
    cudaFuncSetAttribute((const void*)mma_gemm<3, float>, cudaFuncAttributeMaxDynamicSharedMemorySize, GEMM_SMEM);
    cudaFuncSetAttribute((const void*)attn_mma_kernel, cudaFuncAttributeMaxDynamicSharedMemorySize, ATTN_SMEM);

    ln_kernel<<<M_DIM, 256>>>(x, g1, be1, h1);
    repack_qkv<<<(QKV_N * C_DIM + 255) / 256, 256>>>(Wq, Wk, Wv);
    dim3 tb(32, 8);
    transpose_f16<<<dim3(C_DIM / 32, C_DIM / 32), tb>>>(Wp, WpT, C_DIM, C_DIM);
    transpose_f16<<<dim3(FF_DIM / 32, C_DIM / 32), tb>>>(W1, W1T, C_DIM, FF_DIM);
    transpose_f16<<<dim3(C_DIM / 32, FF_DIM / 32), tb>>>(W2, W2T, FF_DIM, C_DIM);

    // QKV: [M,256] @ [256,768] -> half
    mma_gemm<0, __half><<<dim3(QKV_N / 128, M_DIM / 128), 256, GEMM_SMEM>>>(
        h1, Wqkv, nullptr, nullptr, qkv, M_DIM, QKV_N, C_DIM);
    attn_mma_kernel<<<dim3(H_DIM, B_DIM), 256, ATTN_SMEM>>>(qkv, attn);
    // proj + bias + residual(x) -> fp32 residual stream
    mma_gemm<3, float><<<dim3(C_DIM / 128, M_DIM / 128), 256, GEMM_SMEM>>>(
        attn, WpT, bp, x, x1, M_DIM, C_DIM, C_DIM);
    ln_kernel<<<M_DIM, 256>>>(x1, g2, be2, h2);
    // FFN up + GELU -> half
    mma_gemm<2, __half><<<dim3(FF_DIM / 128, M_DIM / 128), 256, GEMM_SMEM>>>(
        h2, W1T, b1, nullptr, ffn1, M_DIM, FF_DIM, C_DIM);
    // FFN down + bias + residual(x1) -> fp32 output
    mma_gemm<3, float><<<dim3(C_DIM / 128, M_DIM / 128), 256, GEMM_SMEM>>>(
        ffn1, W2T, b2, x1, out, M_DIM, C_DIM, FF_DIM);
}

// round 16
// speedup vs baseline: 1.5359x; 1.3103x over previous
#include <cuda_runtime.h>
#include <cuda_fp16.h>
#include <math.h>
#include <stdint.h>

#define C_DIM 256
#define H_DIM 16
#define HS_DIM 16
#define B_DIM 64
#define T_DIM 256
#define M_DIM 16384
#define FF_DIM 1024
#define QKV_N 768
#define LN_EPS 1e-5f

// ---------------- scratch (half activations/weights; fp32 residual stream) ---
__device__ __half g_h1[M_DIM * C_DIM];
__device__ __half g_qkv[M_DIM * QKV_N];
__device__ __half g_attn[M_DIM * C_DIM];
__device__ float  g_x1[M_DIM * C_DIM];
__device__ __half g_h2[M_DIM * C_DIM];
__device__ __half g_ffn1[M_DIM * FF_DIM];
__device__ __half g_Wqkv[QKV_N * C_DIM];   // [N,K] K-major
__device__ __half g_WpT[C_DIM * C_DIM];
__device__ __half g_W1T[FF_DIM * C_DIM];
__device__ __half g_W2T[C_DIM * FF_DIM];

// ---------------- helpers ----------------------------------------------------
__device__ __forceinline__ uint32_t smem_u32(const void* p) {
    uint32_t a;
    asm("{ .reg .u64 t; cvta.to.shared.u64 t, %1; cvt.u32.u64 %0, t; }" : "=r"(a) : "l"(p));
    return a;
}
static __device__ __forceinline__ void cp_async16(uint32_t dst, const void* src) {
    asm volatile("cp.async.cg.shared.global [%0], [%1], 16;" :: "r"(dst), "l"(src) : "memory");
}
#define CP_COMMIT() asm volatile("cp.async.commit_group;" ::: "memory")
template <int N> __device__ __forceinline__ void cp_wait() {
    asm volatile("cp.async.wait_group %0;" :: "n"(N) : "memory");
}

// fp16 mma m16n8k16, fp32 accum
__device__ __forceinline__ void mma_f16(float* c, uint32_t a0, uint32_t a1,
                                        uint32_t a2, uint32_t a3,
                                        uint32_t b0, uint32_t b1) {
    asm volatile(
        "mma.sync.aligned.m16n8k16.row.col.f32.f16.f16.f32 "
        "{%0,%1,%2,%3}, {%4,%5,%6,%7}, {%8,%9}, {%0,%1,%2,%3};"
        : "+f"(c[0]), "+f"(c[1]), "+f"(c[2]), "+f"(c[3])
        : "r"(a0), "r"(a1), "r"(a2), "r"(a3), "r"(b0), "r"(b1));
}

__device__ __forceinline__ void store2(float* out, size_t idx, float x, float y) {
    *(float2*)&out[idx] = make_float2(x, y);
}
__device__ __forceinline__ void store2(__half* out, size_t idx, float x, float y) {
    *(__half2*)&out[idx] = __floats2half2_rn(x, y);
}

// ---------------- LayerNorm (fp32 in, half out) ------------------------------
__global__ void ln_kernel(const float* __restrict__ x, const float* __restrict__ g,
                          const float* __restrict__ b, __half* __restrict__ out) {
    int row = blockIdx.x, tid = threadIdx.x;
    float v = x[(size_t)row * C_DIM + tid];
    float s = v, s2 = v * v;
    #pragma unroll
    for (int o = 16; o; o >>= 1) {
        s += __shfl_xor_sync(0xFFFFFFFFu, s, o);
        s2 += __shfl_xor_sync(0xFFFFFFFFu, s2, o);
    }
    __shared__ float ws[8], ws2[8];
    int w = tid >> 5, l = tid & 31;
    if (l == 0) { ws[w] = s; ws2[w] = s2; }
    __syncthreads();
    if (tid < 32) {
        float t1 = (tid < 8) ? ws[tid] : 0.f;
        float t2 = (tid < 8) ? ws2[tid] : 0.f;
        #pragma unroll
        for (int o = 4; o; o >>= 1) {
            t1 += __shfl_xor_sync(0xFFFFFFFFu, t1, o);
            t2 += __shfl_xor_sync(0xFFFFFFFFu, t2, o);
        }
        if (tid == 0) { ws[0] = t1; ws2[0] = t2; }
    }
    __syncthreads();
    float mean = ws[0] * (1.f / C_DIM);
    float var = ws2[0] * (1.f / C_DIM) - mean * mean;
    out[(size_t)row * C_DIM + tid] =
        __float2half_rn((v - mean) * rsqrtf(var + LN_EPS) * g[tid] + b[tid]);
}

// ---------------- weight repacks ---------------------------------------------
__global__ void repack_qkv(const float* __restrict__ Wq, const float* __restrict__ Wk,
                           const float* __restrict__ Wv) {
    int i = blockIdx.x * blockDim.x + threadIdx.x;
    if (i >= QKV_N * C_DIM) return;
    int n = i >> 8, k = i & 255;
    int sel = n >> 8, nn = n & 255;
    int h = nn >> 4, d = nn & 15;
    int src = h * (C_DIM * HS_DIM) + k * HS_DIM + d;
    const float* W = (sel == 0) ? Wq : (sel == 1) ? Wk : Wv;
    g_Wqkv[i] = __float2half_rn(W[src]);
}

__global__ void transpose_f16(const float* __restrict__ src, __half* __restrict__ dst,
                              int rows, int cols) {
    __shared__ float tile[32][33];
    int bx = blockIdx.x * 32, by = blockIdx.y * 32;
    int tx = threadIdx.x, ty = threadIdx.y;
    #pragma unroll
    for (int j = 0; j < 32; j += 8)
        tile[ty + j][tx] = src[(size_t)(by + ty + j) * cols + bx + tx];
    __syncthreads();
    #pragma unroll
    for (int j = 0; j < 32; j += 8)
        dst[(size_t)(bx + ty + j) * rows + by + tx] = __float2half_rn(tile[tx][ty + j]);
}

// ---------------- fp16 mma.sync GEMM (R15, unchanged: best measured) ---------
#define PAD_H  40
#define TILE_B (128 * PAD_H * 2)
#define STAGE_B (2 * TILE_B)
#define GEMM_SMEM (3 * STAGE_B)

__device__ __forceinline__ void load_tile(uint32_t sdst, const __half* __restrict__ gp,
                                          int ld, int row0, int kc, int tid) {
    #pragma unroll
    for (int i = 0; i < 2; i++) {
        int f = i * 256 + tid;
        int row = f >> 2;
        int seg = f & 3;
        cp_async16(sdst + (uint32_t)(row * 80 + seg * 16),
                   gp + (size_t)(row0 + row) * ld + kc + seg * 8);
    }
}

template <int EPI, typename OutT>
__global__ __launch_bounds__(256, 2) void mma_gemm(
    const __half* __restrict__ A, const __half* __restrict__ Bw,
    const float* __restrict__ bias, const float* __restrict__ resid,
    OutT* __restrict__ out, int M, int N, int K) {
    extern __shared__ __half smem[];
    uint32_t sb = smem_u32(smem);
    int tid = threadIdx.x, wid = tid >> 5, lane = tid & 31;
    int g = lane >> 2, t = lane & 3;
    int warpM = wid & 1, warpN = wid >> 1;
    int mbase = warpM * 64, nbase = warpN * 32;
    int bm = blockIdx.y * 128, bn = blockIdx.x * 128;
    int nc = K >> 5;

    float acc[4][4][4];
    #pragma unroll
    for (int i = 0; i < 4; i++)
        #pragma unroll
        for (int j = 0; j < 4; j++)
            #pragma unroll
            for (int e = 0; e < 4; e++) acc[i][j][e] = 0.f;

    load_tile(sb, A, K, bm, 0, tid);
    load_tile(sb + TILE_B, Bw, K, bn, 0, tid);
    CP_COMMIT();
    load_tile(sb + STAGE_B, A, K, bm, 32, tid);
    load_tile(sb + STAGE_B + TILE_B, Bw, K, bn, 32, tid);
    CP_COMMIT();

    for (int c = 0; c < nc; c++) {
        if (c < nc - 1) cp_wait<1>(); else cp_wait<0>();
        __syncthreads();

        if (c + 2 < nc) {
            uint32_t st = sb + ((c + 2) % 3) * STAGE_B;
            load_tile(st, A, K, bm, (c + 2) << 5, tid);
            load_tile(st + TILE_B, Bw, K, bn, (c + 2) << 5, tid);
            CP_COMMIT();
        }

        const __half* sA = smem + (size_t)(c % 3) * (STAGE_B / 2);
        const __half* sB = sA + 128 * PAD_H;
        #pragma unroll
        for (int kk = 0; kk < 2; kk++) {
            int k0 = kk * 16 + 2 * t;
            uint32_t bf[4][2];
            #pragma unroll
            for (int nt = 0; nt < 4; nt++) {
                int rn = nbase + nt * 8 + g;
                bf[nt][0] = *(const uint32_t*)&sB[rn * PAD_H + k0];
                bf[nt][1] = *(const uint32_t*)&sB[rn * PAD_H + k0 + 8];
            }
            #pragma unroll
            for (int mt = 0; mt < 4; mt++) {
                int r0 = mbase + mt * 16 + g;
                uint32_t a0 = *(const uint32_t*)&sA[r0 * PAD_H + k0];
                uint32_t a1 = *(const uint32_t*)&sA[(r0 + 8) * PAD_H + k0];
                uint32_t a2 = *(const uint32_t*)&sA[r0 * PAD_H + k0 + 8];
                uint32_t a3 = *(const uint32_t*)&sA[(r0 + 8) * PAD_H + k0 + 8];
                #pragma unroll
                for (int nt = 0; nt < 4; nt++)
                    mma_f16(acc[mt][nt], a0, a1, a2, a3, bf[nt][0], bf[nt][1]);
            }
        }
    }

    #pragma unroll
    for (int mt = 0; mt < 4; mt++) {
        int row = bm + mbase + mt * 16 + g;
        #pragma unroll
        for (int nt = 0; nt < 4; nt++) {
            int col = bn + nbase + nt * 8 + 2 * t;
            float v0x = acc[mt][nt][0], v0y = acc[mt][nt][1];
            float v1x = acc[mt][nt][2], v1y = acc[mt][nt][3];
            if (EPI >= 2) {
                float2 bv = *(const float2*)&bias[col];
                v0x += bv.x; v0y += bv.y; v1x += bv.x; v1y += bv.y;
            }
            if (EPI == 2) {
                v0x = 0.5f * v0x * (1.f + erff(v0x * 0.70710678118654752f));
                v0y = 0.5f * v0y * (1.f + erff(v0y * 0.70710678118654752f));
                v1x = 0.5f * v1x * (1.f + erff(v1x * 0.70710678118654752f));
                v1y = 0.5f * v1y * (1.f + erff(v1y * 0.70710678118654752f));
            }
            if (EPI == 3) {
                float2 r0 = *(const float2*)&resid[(size_t)row * N + col];
                float2 r1 = *(const float2*)&resid[(size_t)(row + 8) * N + col];
                v0x += r0.x; v0y += r0.y; v1x += r1.x; v1y += r1.y;
            }
            store2(out, (size_t)row * N + col, v0x, v0y);
            store2(out, (size_t)(row + 8) * N + col, v1x, v1y);
        }
    }
}

// ---------------- fp16 tensor-core flash attention ---------------------------
// Q/K staged half [256][24] (conflict-free g*12+t), V transposed [16][264],
// P half per-warp [16][72]. QK^T: 1 k16 step (HS=16), 8 MMAs/tile.
// PV: 4 k16 steps x 2 n-tiles = 8 MMAs/tile. S/softmax in fp32; scale 1/16
// applied to S accumulators post-MMA (exact).
#define APAD 24
#define VPAD 264
#define PPAD 72
#define SQH 0
#define SKH (256 * APAD)
#define SVT (512 * APAD)
#define SPH (512 * APAD + 16 * VPAD)
#define ATTN_SMEM ((SPH + 8 * 16 * PPAD) * 2)

__global__ __launch_bounds__(256) void attn_mma_kernel(const __half* __restrict__ qkv,
                                                       __half* __restrict__ out) {
    extern __shared__ __half smh[];
    __half* sQ = smh + SQH;
    __half* sK = smh + SKH;
    __half* sVt = smh + SVT;
    int h = blockIdx.x, b = blockIdx.y;
    int tid = threadIdx.x, w = tid >> 5, lane = tid & 31;
    int g = lane >> 2, t = lane & 3;
    __half* sP = smh + SPH + w * (16 * PPAD);

    {
        const __half* rp = qkv + (size_t)(b * T_DIM + tid) * QKV_N + h * 16;
        *(uint4*)&sQ[tid * APAD] = *(const uint4*)&rp[0];
        *(uint4*)&sQ[tid * APAD + 8] = *(const uint4*)&rp[8];
        *(uint4*)&sK[tid * APAD] = *(const uint4*)&rp[256];
        *(uint4*)&sK[tid * APAD + 8] = *(const uint4*)&rp[264];
        #pragma unroll
        for (int d = 0; d < 16; d++) sVt[d * VPAD + tid] = rp[512 + d];
    }
    __syncthreads();

    #pragma unroll
    for (int half_i = 0; half_i < 2; half_i++) {
        int rt = half_i ? (15 - w) : w;
        int r0 = rt * 16;
        int nkt = (rt >> 2) + 1;
        float m0 = -1e30f, m1 = -1e30f, l0 = 0.f, l1 = 0.f;
        float o[2][4] = {};

        // Q fragments: constant across key tiles (HS=16 = one k16 step)
        uint32_t qa0 = *(const uint32_t*)&sQ[(r0 + g) * APAD + 2 * t];
        uint32_t qa1 = *(const uint32_t*)&sQ[(r0 + g + 8) * APAD + 2 * t];
        uint32_t qa2 = *(const uint32_t*)&sQ[(r0 + g) * APAD + 8 + 2 * t];
        uint32_t qa3 = *(const uint32_t*)&sQ[(r0 + g + 8) * APAD + 8 + 2 * t];

        for (int kt = 0; kt < nkt; kt++) {
            int kb = kt * 64;
            float s[8][4];
            #pragma unroll
            for (int nt = 0; nt < 8; nt++) {
                s[nt][0] = 0.f; s[nt][1] = 0.f; s[nt][2] = 0.f; s[nt][3] = 0.f;
            }
            #pragma unroll
            for (int nt = 0; nt < 8; nt++) {
                int rn = kb + nt * 8 + g;
                uint32_t b0 = *(const uint32_t*)&sK[rn * APAD + 2 * t];
                uint32_t b1 = *(const uint32_t*)&sK[rn * APAD + 8 + 2 * t];
                mma_f16(s[nt], qa0, qa1, qa2, qa3, b0, b1);
            }
            #pragma unroll
            for (int nt = 0; nt < 8; nt++) {
                s[nt][0] *= 0.0625f; s[nt][1] *= 0.0625f;
                s[nt][2] *= 0.0625f; s[nt][3] *= 0.0625f;
            }
            if (kt == nkt - 1) {
                int rlo = r0 + g, rhi = r0 + g + 8;
                #pragma unroll
                for (int nt = 0; nt < 8; nt++) {
                    int c0 = kb + nt * 8 + 2 * t;
                    if (c0 > rlo) s[nt][0] = -1e30f;
                    if (c0 + 1 > rlo) s[nt][1] = -1e30f;
                    if (c0 > rhi) s[nt][2] = -1e30f;
                    if (c0 + 1 > rhi) s[nt][3] = -1e30f;
                }
            }
            float rm0 = -1e30f, rm1 = -1e30f;
            #pragma unroll
            for (int nt = 0; nt < 8; nt++) {
                rm0 = fmaxf(rm0, fmaxf(s[nt][0], s[nt][1]));
                rm1 = fmaxf(rm1, fmaxf(s[nt][2], s[nt][3]));
            }
            rm0 = fmaxf(rm0, __shfl_xor_sync(0xFFFFFFFFu, rm0, 1));
            rm0 = fmaxf(rm0, __shfl_xor_sync(0xFFFFFFFFu, rm0, 2));
            rm1 = fmaxf(rm1, __shfl_xor_sync(0xFFFFFFFFu, rm1, 1));
            rm1 = fmaxf(rm1, __shfl_xor_sync(0xFFFFFFFFu, rm1, 2));
            float mn0 = fmaxf(m0, rm0), mn1 = fmaxf(m1, rm1);
            float cf0 = __expf(m0 - mn0), cf1 = __expf(m1 - mn1);
            m0 = mn0; m1 = mn1;
            l0 *= cf0; l1 *= cf1;
            o[0][0] *= cf0; o[0][1] *= cf0; o[1][0] *= cf0; o[1][1] *= cf0;
            o[0][2] *= cf1; o[0][3] *= cf1; o[1][2] *= cf1; o[1][3] *= cf1;

            float ps0 = 0.f, ps1 = 0.f;
            #pragma unroll
            for (int nt = 0; nt < 8; nt++) {
                float p0 = __expf(s[nt][0] - m0);
                float p1 = __expf(s[nt][1] - m0);
                float p2 = __expf(s[nt][2] - m1);
                float p3 = __expf(s[nt][3] - m1);
                ps0 += p0 + p1; ps1 += p2 + p3;
                int cc = nt * 8 + 2 * t;
                *(__half2*)&sP[g * PPAD + cc] = __floats2half2_rn(p0, p1);
                *(__half2*)&sP[(g + 8) * PPAD + cc] = __floats2half2_rn(p2, p3);
            }
            ps0 += __shfl_xor_sync(0xFFFFFFFFu, ps0, 1);
            ps0 += __shfl_xor_sync(0xFFFFFFFFu, ps0, 2);
            ps1 += __shfl_xor_sync(0xFFFFFFFFu, ps1, 1);
            ps1 += __shfl_xor_sync(0xFFFFFFFFu, ps1, 2);
            l0 += ps0; l1 += ps1;
            __syncwarp();

            #pragma unroll
            for (int ks = 0; ks < 4; ks++) {
                int k0 = ks * 16 + 2 * t;
                uint32_t a0 = *(const uint32_t*)&sP[g * PPAD + k0];
                uint32_t a1 = *(const uint32_t*)&sP[(g + 8) * PPAD + k0];
                uint32_t a2 = *(const uint32_t*)&sP[g * PPAD + k0 + 8];
                uint32_t a3 = *(const uint32_t*)&sP[(g + 8) * PPAD + k0 + 8];
                #pragma unroll
                for (int nt2 = 0; nt2 < 2; nt2++) {
                    int n = nt2 * 8 + g;
                    uint32_t b0 = *(const uint32_t*)&sVt[n * VPAD + kb + k0];
                    uint32_t b1 = *(const uint32_t*)&sVt[n * VPAD + kb + k0 + 8];
                    mma_f16(o[nt2], a0, a1, a2, a3, b0, b1);
                }
            }
            __syncwarp();
        }

        float i0 = 1.f / l0, i1 = 1.f / l1;
        #pragma unroll
        for (int nt2 = 0; nt2 < 2; nt2++) {
            int col = h * 16 + nt2 * 8 + 2 * t;
            *(__half2*)&out[(size_t)(b * T_DIM + r0 + g) * C_DIM + col] =
                __floats2half2_rn(o[nt2][0] * i0, o[nt2][1] * i0);
            *(__half2*)&out[(size_t)(b * T_DIM + r0 + g + 8) * C_DIM + col] =
                __floats2half2_rn(o[nt2][2] * i1, o[nt2][3] * i1);
        }
    }
}

// ---------------- launch -----------------------------------------------------
extern "C" void kernel_launch(void* const* d_in, const int* in_sizes, int n_in,
                              void* d_out, int out_size) {
    const float* x = (const float*)d_in[0];
    const float* Wq = (const float*)d_in[1];
    const float* Wk = (const float*)d_in[2];
    const float* Wv = (const float*)d_in[3];
    const float* Wp = (const float*)d_in[4];
    const float* bp = (const float*)d_in[5];
    const float* W1 = (const float*)d_in[6];
    const float* b1 = (const float*)d_in[7];
    const float* W2 = (const float*)d_in[8];
    const float* b2 = (const float*)d_in[9];
    const float* g1 = (const float*)d_in[10];
    const float* be1 = (const float*)d_in[11];
    const float* g2 = (const float*)d_in[12];
    const float* be2 = (const float*)d_in[13];
    float* out = (float*)d_out;

    __half *h1, *qkv, *attn, *h2, *ffn1, *Wqkv, *WpT, *W1T, *W2T;
    float* x1;
    cudaGetSymbolAddress((void**)&h1, g_h1);
    cudaGetSymbolAddress((void**)&qkv, g_qkv);
    cudaGetSymbolAddress((void**)&attn, g_attn);
    cudaGetSymbolAddress((void**)&x1, g_x1);
    cudaGetSymbolAddress((void**)&h2, g_h2);
    cudaGetSymbolAddress((void**)&ffn1, g_ffn1);
    cudaGetSymbolAddress((void**)&Wqkv, g_Wqkv);
    cudaGetSymbolAddress((void**)&WpT, g_WpT);
    cudaGetSymbolAddress((void**)&W1T, g_W1T);
    cudaGetSymbolAddress((void**)&W2T, g_W2T);

    cudaFuncSetAttribute((const void*)mma_gemm<0, __half>, cudaFuncAttributeMaxDynamicSharedMemorySize, GEMM_SMEM);
    cudaFuncSetAttribute((const void*)mma_gemm<2, __half>, cudaFuncAttributeMaxDynamicSharedMemorySize, GEMM_SMEM);
    cudaFuncSetAttribute((const void*)mma_gemm<3, float>, cudaFuncAttributeMaxDynamicSharedMemorySize, GEMM_SMEM);
    cudaFuncSetAttribute((const void*)attn_mma_kernel, cudaFuncAttributeMaxDynamicSharedMemorySize, ATTN_SMEM);

    ln_kernel<<<M_DIM, 256>>>(x, g1, be1, h1);
    repack_qkv<<<(QKV_N * C_DIM + 255) / 256, 256>>>(Wq, Wk, Wv);
    dim3 tb(32, 8);
    transpose_f16<<<dim3(C_DIM / 32, C_DIM / 32), tb>>>(Wp, WpT, C_DIM, C_DIM);
    transpose_f16<<<dim3(FF_DIM / 32, C_DIM / 32), tb>>>(W1, W1T, C_DIM, FF_DIM);
    transpose_f16<<<dim3(C_DIM / 32, FF_DIM / 32), tb>>>(W2, W2T, FF_DIM, C_DIM);

    // QKV: [M,256] @ [256,768] -> half
    mma_gemm<0, __half><<<dim3(QKV_N / 128, M_DIM / 128), 256, GEMM_SMEM>>>(
        h1, Wqkv, nullptr, nullptr, qkv, M_DIM, QKV_N, C_DIM);
    attn_mma_kernel<<<dim3(H_DIM, B_DIM), 256, ATTN_SMEM>>>(qkv, attn);
    // proj + bias + residual(x) -> fp32 residual stream
    mma_gemm<3, float><<<dim3(C_DIM / 128, M_DIM / 128), 256, GEMM_SMEM>>>(
        attn, WpT, bp, x, x1, M_DIM, C_DIM, C_DIM);
    ln_kernel<<<M_DIM, 256>>>(x1, g2, be2, h2);
    // FFN up + GELU -> half
    mma_gemm<2, __half><<<dim3(FF_DIM / 128, M_DIM / 128), 256, GEMM_SMEM>>>(
        h2, W1T, b1, nullptr, ffn1, M_DIM, FF_DIM, C_DIM);
    // FFN down + bias + residual(x1) -> fp32 output
    mma_gemm<3, float><<<dim3(C_DIM / 128, M_DIM / 128), 256, GEMM_SMEM>>>(
        ffn1, W2T, b2, x1, out, M_DIM, C_DIM, FF_DIM);
}